// round 8
// baseline (speedup 1.0000x reference)
#include <cuda_runtime.h>
#include <math.h>
#include <stdint.h>
#include <stddef.h>

// ---------------- problem constants ----------------
#define Bn   32
#define Tn   1024
#define Dn   1024
#define Sn   256
#define KF   3
#define Mrows (Bn*Tn)                 // 32768
#define IOFF  ((size_t)Bn*Tn*Dn)      // 33554432 (indices start in d_out)
#define LOFF  (IOFF + (size_t)Bn*Tn)  // total scalar slot

#define GRU_CTAS    148
#define GRU_WARPS   7
#define GRU_THREADS (GRU_WARPS*32)    // 224
#define HS_PITCH    1028              // 1028 % 32 == 4 -> conflict-free LDS.128
#define GRU_SMEM    (32*HS_PITCH*4 + 32*4)

// ---------------- packed f32x2 helpers (Blackwell FFMA2) ---------------------
__device__ __forceinline__ unsigned long long ffma2(unsigned long long a,
                                                    unsigned long long b,
                                                    unsigned long long c) {
    unsigned long long d;
    asm("fma.rn.f32x2 %0, %1, %2, %3;" : "=l"(d) : "l"(a), "l"(b), "l"(c));
    return d;
}
__device__ __forceinline__ unsigned long long rep2(float x) {
    unsigned long long r;
    asm("mov.b64 %0, {%1, %1};" : "=l"(r) : "f"(x));
    return r;
}
__device__ __forceinline__ void unpack2(unsigned long long v, float& lo, float& hi) {
    asm("mov.b64 {%0, %1}, %2;" : "=f"(lo), "=f"(hi) : "l"(v));
}

// ---------------- device scratch (no allocations) ----------------
__device__ float g_dots[(size_t)Mrows * Sn];   // 33.5 MB : 2*F.C^T
__device__ float g_H  [(size_t)Mrows * Dn];    // 134 MB, row = t*Bn + b
__device__ float g_Hp [(size_t)Mrows * Dn];    // 134 MB, same layout
__device__ float g_GI [(size_t)Sn * 3*Dn];     // 3 MB
__device__ float g_hT [2][Bn * Dn];            // double-buffered h, [b][k]
__device__ float g_rnorm[Mrows];
__device__ float g_cnorm[Sn];
__device__ float g_zbias[Sn];                  // zero-initialized, never written
__device__ int   g_idx[Mrows];                 // row = b*Tn + t
__device__ float g_mse_arr[Mrows/8];           // 4096 per-block partials
__device__ float g_cp_arr[KF*(Tn-1)];          // 3069 slots
__device__ unsigned g_bar;

// ---------------- init ----------------
__global__ void init_kernel() {
    int i = blockIdx.x * 256 + threadIdx.x;
    if (i < Bn*Dn) g_hT[0][i] = 0.f;
    if (i == 0) g_bar = 0u;
}

// ---------------- row squared norms (8 rows/block, warp per row) -------------
__global__ void rownorm_kernel(const float* __restrict__ X,
                               float* __restrict__ out, int rows) {
    int wid = threadIdx.x >> 5, lane = threadIdx.x & 31;
    int row = blockIdx.x * 8 + wid;
    if (row >= rows) return;
    const float4* x = (const float4*)(X + (size_t)row * Dn);
    float s = 0.f;
#pragma unroll
    for (int j = 0; j < 8; j++) {
        float4 v = x[j*32 + lane];
        s += v.x*v.x + v.y*v.y + v.z*v.z + v.w*v.w;
    }
#pragma unroll
    for (int off = 16; off; off >>= 1) s += __shfl_xor_sync(0xffffffffu, s, off);
    if (lane == 0) out[row] = s;
}

// ---------------- SGEMM: C = alpha*A*B^T + bias[col]  (FFMA2 core) -----------
// A: MxK row-major, B: NxK row-major, C: MxN. M,N mult of 128, K mult of 16.
// Per-element accumulation chain identical to the scalar version (packed pairs
// along j), so the dots-GEMM result is bit-identical to round 6.
__global__ __launch_bounds__(256, 2)
void sgemm_nt(const float* __restrict__ A, const float* __restrict__ Bm,
              float* __restrict__ C, const float* __restrict__ bias,
              int M, int N, int K, float alpha)
{
    __shared__ float As[16][128];
    __shared__ float Bs[16][128];
    const int tid = threadIdx.x;
    const int tx = tid & 15, ty = tid >> 4;
    const float* Ab = A + (size_t)blockIdx.y * 128 * K;
    const float* Bb = Bm + (size_t)blockIdx.x * 128 * K;

    unsigned long long acc2[8][4];   // acc2[i][j] packs (acc[i][2j], acc[i][2j+1])
#pragma unroll
    for (int i = 0; i < 8; i++)
#pragma unroll
        for (int j = 0; j < 4; j++) acc2[i][j] = 0ull;   // (+0.f, +0.f)

    for (int kt = 0; kt < K; kt += 16) {
#pragma unroll
        for (int r = 0; r < 2; r++) {
            int f   = tid + r * 256;           // 0..511
            int row = f >> 2;                  // 0..127
            int c4  = (f & 3) << 2;            // 0,4,8,12
            float4 va = *(const float4*)(Ab + (size_t)row * K + kt + c4);
            As[c4+0][row] = va.x; As[c4+1][row] = va.y;
            As[c4+2][row] = va.z; As[c4+3][row] = va.w;
            float4 vb = *(const float4*)(Bb + (size_t)row * K + kt + c4);
            Bs[c4+0][row] = vb.x; Bs[c4+1][row] = vb.y;
            Bs[c4+2][row] = vb.z; Bs[c4+3][row] = vb.w;
        }
        __syncthreads();
#pragma unroll
        for (int kk = 0; kk < 16; kk++) {
            float a[8];
            unsigned long long b2[4];
            *(float4*)&a[0] = *(const float4*)&As[kk][ty*8];
            *(float4*)&a[4] = *(const float4*)&As[kk][ty*8+4];
            *(ulonglong2*)&b2[0] = *(const ulonglong2*)&Bs[kk][tx*8];
            *(ulonglong2*)&b2[2] = *(const ulonglong2*)&Bs[kk][tx*8+4];
#pragma unroll
            for (int i = 0; i < 8; i++) {
                unsigned long long a2 = rep2(a[i]);
#pragma unroll
                for (int j = 0; j < 4; j++)
                    acc2[i][j] = ffma2(a2, b2[j], acc2[i][j]);
            }
        }
        __syncthreads();
    }
#pragma unroll
    for (int i = 0; i < 8; i++) {
        size_t row = (size_t)blockIdx.y * 128 + ty*8 + i;
#pragma unroll
        for (int j = 0; j < 8; j += 4) {
            int col = blockIdx.x * 128 + tx*8 + j;
            float c0, c1, c2, c3;
            unpack2(acc2[i][j/2],     c0, c1);
            unpack2(acc2[i][j/2 + 1], c2, c3);
            float4 o;
            o.x = alpha * c0 + bias[col+0];
            o.y = alpha * c1 + bias[col+1];
            o.z = alpha * c2 + bias[col+2];
            o.w = alpha * c3 + bias[col+3];
            *(float4*)(C + row * (size_t)N + col) = o;
        }
    }
}

// ---------------- argmin (reference-exact rounding) + gather + mse -----------
__global__ void argmin_kernel(const float* __restrict__ codebook,
                              float* __restrict__ dout) {
    int wid = threadIdx.x >> 5, lane = threadIdx.x & 31;
    int row = blockIdx.x * 8 + wid;
    __shared__ float part[8];
    __shared__ float cn_s[Sn];
    if (threadIdx.x < Sn) cn_s[threadIdx.x] = g_cnorm[threadIdx.x];
    __syncthreads();

    const float rn = g_rnorm[row];
    float bv = 3.4e38f; int bi = 0;
#pragma unroll
    for (int j = 0; j < 8; j++) {
        int i = j * 32 + lane;                   // ascending per lane
        float dot2 = g_dots[(size_t)row * Sn + i];         // = 2 * f.c_i
        float v = __fadd_rn(__fsub_rn(rn, dot2), cn_s[i]); // (A-B)+C, no FMA
        if (v < bv) { bv = v; bi = i; }          // first min per lane
    }
#pragma unroll
    for (int off = 16; off; off >>= 1) {
        float ov = __shfl_xor_sync(0xffffffffu, bv, off);
        int   oi = __shfl_xor_sync(0xffffffffu, bi, off);
        if (ov < bv || (ov == bv && oi < bi)) { bv = ov; bi = oi; }
    }
    if (lane == 0) {
        g_idx[row] = bi;
        dout[IOFF + row] = (float)bi;
        part[wid] = bv;                          // ||f - c*||^2 (quantized)
    }
    const float4* c4 = (const float4*)(codebook + (size_t)bi * Dn);
    float4* o4 = (float4*)(dout + (size_t)row * Dn);
#pragma unroll
    for (int j = 0; j < 8; j++) o4[j*32 + lane] = __ldg(c4 + j*32 + lane);

    __syncthreads();
    if (threadIdx.x == 0) {
        float s = 0.f;
#pragma unroll
        for (int w = 0; w < 8; w++) s += part[w];
        g_mse_arr[blockIdx.x] = s;
    }
}

// ---------------- persistent GRU recurrence ----------------------------------
__device__ __forceinline__ unsigned ld_acquire_u32(const unsigned* p) {
    unsigned v;
    asm volatile("ld.acquire.gpu.u32 %0, [%1];" : "=r"(v) : "l"(p) : "memory");
    return v;
}

__global__ __launch_bounds__(GRU_THREADS, 1)
void gru_kernel(const float* __restrict__ W_hh, const float* __restrict__ b_hh)
{
    extern __shared__ float sh[];                 // [32][HS_PITCH] + 32 codes
    int* codes_s = (int*)(sh + 32 * HS_PITCH);
    const int tid  = threadIdx.x;
    const int wid  = tid >> 5, lane = tid & 31;
    const int d    = blockIdx.x * GRU_WARPS + wid;
    const bool active = (d < Dn);

    float bh_r = 0.f, bh_z = 0.f, bh_n = 0.f;
    const ulonglong2 *wr2 = 0, *wz2 = 0, *wn2 = 0;
    if (active) {
        bh_r = b_hh[d]; bh_z = b_hh[Dn + d]; bh_n = b_hh[2*Dn + d];
        wr2 = (const ulonglong2*)(W_hh + (size_t)d        * Dn);
        wz2 = (const ulonglong2*)(W_hh + (size_t)(Dn + d) * Dn);
        wn2 = (const ulonglong2*)(W_hh + (size_t)(2*Dn+d) * Dn);
    }

    for (int t = 0; t < Tn; t++) {
        const float4* hin4 = (const float4*)g_hT[t & 1];
        float*        hout = g_hT[(t + 1) & 1];

        // stage full h (32x1024 f32) into smem via L2-only loads (.cg) so the
        // L1-resident W_hh rows (84 KB/SM) are never evicted by the stream.
        for (int i = tid; i < (Bn*Dn)/4; i += GRU_THREADS) {
            int b  = i >> 8;                      // 256 float4 per batch row
            int kf = i & 255;
            float4 v = __ldcg(hin4 + i);
            *(float4*)(sh + b * HS_PITCH + kf * 4) = v;
        }
        if (tid < Bn) codes_s[tid] = g_idx[tid * Tn + t];
        __syncthreads();

        if (active) {
            int code = codes_s[lane];
            const float* gi = g_GI + (size_t)code * (3*Dn);
            float gir = __ldcg(gi + d);           // .cg: keep L1 for W
            float giz = __ldcg(gi + Dn + d);
            float gin = __ldcg(gi + 2*Dn + d);

            const ulonglong2* hrow = (const ulonglong2*)(sh + lane * HS_PITCH);
            unsigned long long ar01 = 0ull, ar23 = 0ull;
            unsigned long long az01 = 0ull, az23 = 0ull;
            unsigned long long an01 = 0ull, an23 = 0ull;
#pragma unroll 4
            for (int q = 0; q < Dn/4; q++) {
                ulonglong2 h2 = hrow[q];          // LDS.128 (2 packed f32 pairs)
                ulonglong2 w1 = __ldg(wr2 + q);   // uniform LDG.128, L1-hit
                ulonglong2 w2 = __ldg(wz2 + q);
                ulonglong2 w3 = __ldg(wn2 + q);
                ar01 = ffma2(w1.x, h2.x, ar01); ar23 = ffma2(w1.y, h2.y, ar23);
                az01 = ffma2(w2.x, h2.x, az01); az23 = ffma2(w2.y, h2.y, az23);
                an01 = ffma2(w3.x, h2.x, an01); an23 = ffma2(w3.y, h2.y, an23);
            }
            float l0,h0,l1,h1;
            unpack2(ar01,l0,h0); unpack2(ar23,l1,h1);
            float ar = (l0+h0) + (l1+h1);
            unpack2(az01,l0,h0); unpack2(az23,l1,h1);
            float az = (l0+h0) + (l1+h1);
            unpack2(an01,l0,h0); unpack2(an23,l1,h1);
            float an = (l0+h0) + (l1+h1);

            float r = 1.f / (1.f + expf(-(ar + bh_r + gir)));
            float z = 1.f / (1.f + expf(-(az + bh_z + giz)));
            float n = tanhf(gin + r * (an + bh_n));
            float hprev = sh[lane * HS_PITCH + d];
            float hnew  = (1.f - z) * n + z * hprev;
            hout[lane * Dn + d] = hnew;
            g_H[((size_t)t * Bn + lane) * Dn + d] = hnew;
        }
        __threadfence();
        __syncthreads();
        if (tid == 0) {
            atomicAdd(&g_bar, 1u);
            unsigned target = (unsigned)GRU_CTAS * (unsigned)(t + 1);
            while (ld_acquire_u32(&g_bar) < target) { }
        }
        __syncthreads();
    }
}

// ---------------- CP loss per (k,t): -log(mean_b sigmoid(Hp.(fpos-fneg))) ----
__global__ void cploss_kernel(const float* __restrict__ features,
                              const int* __restrict__ neg_idx)
{
    int t  = blockIdx.x;            // 0..Tn-2
    int kf = blockIdx.y;            // 0..KF-1
    int k  = kf + 1;
    int slot = kf * (Tn - 1) + t;
    if (t >= Tn - k) { if (threadIdx.x == 0) g_cp_arr[slot] = 0.f; return; }

    __shared__ float sig_s[Bn];
    int wid = threadIdx.x >> 5, lane = threadIdx.x & 31;
#pragma unroll
    for (int bi = 0; bi < 4; bi++) {
        int b = wid * 4 + bi;
        const float4* hp = (const float4*)(g_Hp + ((size_t)t * Bn + b) * Dn);
        const float4* fp = (const float4*)(features + ((size_t)b * Tn + (t + k)) * Dn);
        int bneg = neg_idx[((size_t)kf * Tn + t) * Bn + b];
        const float4* fn = (const float4*)(features + ((size_t)bneg * Tn + t) * Dn);
        float s = 0.f;
#pragma unroll
        for (int j = 0; j < 8; j++) {
            float4 h4 = hp[j*32 + lane];
            float4 p4 = fp[j*32 + lane];
            float4 n4 = fn[j*32 + lane];
            s += h4.x*(p4.x-n4.x) + h4.y*(p4.y-n4.y)
               + h4.z*(p4.z-n4.z) + h4.w*(p4.w-n4.w);
        }
#pragma unroll
        for (int off = 16; off; off >>= 1) s += __shfl_xor_sync(0xffffffffu, s, off);
        if (lane == 0) sig_s[b] = 1.f / (1.f + expf(-s));
    }
    __syncthreads();
    if (threadIdx.x == 0) {
        float m = 0.f;
#pragma unroll
        for (int b = 0; b < Bn; b++) m += sig_s[b];
        g_cp_arr[slot] = -logf(m * (1.f / (float)Bn));
    }
}

// ---------------- final deterministic reduction -------------------------------
__global__ void finalize_kernel(float* __restrict__ dout) {
    __shared__ float red[256];
    int tid = threadIdx.x;
    float s = 0.f;
    for (int i = tid; i < KF*(Tn-1); i += 256) s += g_cp_arr[i];
    red[tid] = s; __syncthreads();
    for (int o = 128; o; o >>= 1) { if (tid < o) red[tid] += red[tid+o]; __syncthreads(); }
    float cp = red[0]; __syncthreads();
    float m = 0.f;
    for (int i = tid; i < Mrows/8; i += 256) m += g_mse_arr[i];
    red[tid] = m; __syncthreads();
    for (int o = 128; o; o >>= 1) { if (tid < o) red[tid] += red[tid+o]; __syncthreads(); }
    if (tid == 0) {
        float mse = red[0] / ((float)Mrows * (float)Dn);
        // commitment == codebook loss numerically -> 1.25 * mse
        dout[LOFF] = cp / (float)(KF * (Tn - KF)) + 1.25f * mse;
    }
}

// ---------------- launch --------------------------------------------------------
extern "C" void kernel_launch(void* const* d_in, const int* in_sizes, int n_in,
                              void* d_out, int out_size) {
    (void)in_sizes; (void)n_in; (void)out_size;
    const float* features = (const float*)d_in[0];
    const float* codebook = (const float*)d_in[1];
    const float* W_ih     = (const float*)d_in[2];
    const float* W_hh     = (const float*)d_in[3];
    const float* b_ih     = (const float*)d_in[4];
    const float* b_hh     = (const float*)d_in[5];
    const float* W_p      = (const float*)d_in[6];
    const float* b_p      = (const float*)d_in[7];
    const int*   neg_idx  = (const int*)d_in[8];
    float* dout = (float*)d_out;

    void *p_rnorm, *p_cnorm, *p_dots, *p_GI, *p_H, *p_Hp, *p_zb;
    cudaGetSymbolAddress(&p_rnorm, g_rnorm);
    cudaGetSymbolAddress(&p_cnorm, g_cnorm);
    cudaGetSymbolAddress(&p_dots,  g_dots);
    cudaGetSymbolAddress(&p_GI,    g_GI);
    cudaGetSymbolAddress(&p_H,     g_H);
    cudaGetSymbolAddress(&p_Hp,    g_Hp);
    cudaGetSymbolAddress(&p_zb,    g_zbias);

    cudaFuncSetAttribute(gru_kernel,
        cudaFuncAttributeMaxDynamicSharedMemorySize, GRU_SMEM);

    init_kernel<<<(Bn*Dn + 255)/256, 256>>>();

    rownorm_kernel<<<Mrows/8, 256>>>(features, (float*)p_rnorm, Mrows);
    rownorm_kernel<<<Sn/8,    256>>>(codebook, (float*)p_cnorm, Sn);

    // dots = 2 * F C^T   (M x S), raw (no bias) so argmin can replicate
    // the reference's (A - B) + C rounding order exactly.
    sgemm_nt<<<dim3(Sn/128, Mrows/128), 256>>>(
        features, codebook, (float*)p_dots, (const float*)p_zb,
        Mrows, Sn, Dn, 2.0f);

    argmin_kernel<<<Mrows/8, 256>>>(codebook, dout);

    // GI = codebook @ W_ih^T + b_ih   (S x 3D)
    sgemm_nt<<<dim3(3*Dn/128, Sn/128), 256>>>(
        codebook, W_ih, (float*)p_GI, b_ih, Sn, 3*Dn, Dn, 1.0f);

    gru_kernel<<<GRU_CTAS, GRU_THREADS, GRU_SMEM>>>(W_hh, b_hh);

    // Hp = H @ W_p^T + b_p   (M x D)
    sgemm_nt<<<dim3(Dn/128, Mrows/128), 256>>>(
        (const float*)p_H, W_p, (float*)p_Hp, b_p, Mrows, Dn, Dn, 1.0f);

    cploss_kernel<<<dim3(Tn-1, KF), 256>>>(features, neg_idx);

    finalize_kernel<<<1, 256>>>(dout);
}

// round 9
// speedup vs baseline: 1.3077x; 1.3077x over previous
#include <cuda_runtime.h>
#include <math.h>
#include <stdint.h>
#include <stddef.h>

// ---------------- problem constants ----------------
#define Bn   32
#define Tn   1024
#define Dn   1024
#define Sn   256
#define KF   3
#define Mrows (Bn*Tn)                 // 32768
#define IOFF  ((size_t)Bn*Tn*Dn)      // 33554432 (indices start in d_out)
#define LOFF  (IOFF + (size_t)Bn*Tn)  // total scalar slot

#define GRU_CTAS    147
#define DPC         7                 // d-columns per CTA (147*7 = 1029 >= 1024)
#define GRU_WARPS   14                // warp pair (p, half) per d-column
#define GRU_THREADS (GRU_WARPS*32)    // 448
#define HS_PITCH    1028              // %32==4 -> conflict-free LDS.128 phases
#define SM_CODES    (32*HS_PITCH)           // float offset of codes[32]
#define SM_PART     (SM_CODES + 32)         // float offset of part[DPC*3*32]
#define GRU_SMEM    ((SM_PART + DPC*3*32)*4)

// ---------------- device scratch (no allocations) ----------------
__device__ float g_dots[(size_t)Mrows * Sn];   // 33.5 MB : 2*F.C^T
__device__ float g_H  [(size_t)Mrows * Dn];    // 134 MB, row = t*Bn + b
__device__ float g_Hp [(size_t)Mrows * Dn];    // 134 MB, same layout
__device__ float g_GI [(size_t)Sn * 3*Dn];     // 3 MB
__device__ float g_hT [2][Bn * Dn];            // double-buffered h, [b][k]
__device__ float g_rnorm[Mrows];
__device__ float g_cnorm[Sn];
__device__ float g_zbias[Sn];                  // zero-initialized, never written
__device__ int   g_idx[Mrows];                 // row = b*Tn + t
__device__ float g_mse_arr[Mrows/8];           // 4096 per-block partials
__device__ float g_cp_arr[KF*(Tn-1)];          // 3069 slots
__device__ unsigned g_bar;

// ---------------- init ----------------
__global__ void init_kernel() {
    int i = blockIdx.x * 256 + threadIdx.x;
    if (i < Bn*Dn) g_hT[0][i] = 0.f;
    if (i == 0) g_bar = 0u;
}

// ---------------- row squared norms (8 rows/block, warp per row) -------------
__global__ void rownorm_kernel(const float* __restrict__ X,
                               float* __restrict__ out, int rows) {
    int wid = threadIdx.x >> 5, lane = threadIdx.x & 31;
    int row = blockIdx.x * 8 + wid;
    if (row >= rows) return;
    const float4* x = (const float4*)(X + (size_t)row * Dn);
    float s = 0.f;
#pragma unroll
    for (int j = 0; j < 8; j++) {
        float4 v = x[j*32 + lane];
        s += v.x*v.x + v.y*v.y + v.z*v.z + v.w*v.w;
    }
#pragma unroll
    for (int off = 16; off; off >>= 1) s += __shfl_xor_sync(0xffffffffu, s, off);
    if (lane == 0) out[row] = s;
}

// ---------------- SGEMM: C = alpha*A*B^T + bias[col]  (scalar FFMA) ----------
// A: MxK row-major, B: NxK row-major, C: MxN. M,N mult of 128, K mult of 16.
// Measured at the fp32 roofline (38.3 TF/s @NAT). Keep scalar: f32x2 is
// half-rate per element on sm_103a (R8 evidence).
__global__ __launch_bounds__(256, 2)
void sgemm_nt(const float* __restrict__ A, const float* __restrict__ Bm,
              float* __restrict__ C, const float* __restrict__ bias,
              int M, int N, int K, float alpha)
{
    __shared__ float As[16][128];
    __shared__ float Bs[16][128];
    const int tid = threadIdx.x;
    const int tx = tid & 15, ty = tid >> 4;
    const float* Ab = A + (size_t)blockIdx.y * 128 * K;
    const float* Bb = Bm + (size_t)blockIdx.x * 128 * K;

    float acc[8][8];
#pragma unroll
    for (int i = 0; i < 8; i++)
#pragma unroll
        for (int j = 0; j < 8; j++) acc[i][j] = 0.f;

    for (int kt = 0; kt < K; kt += 16) {
#pragma unroll
        for (int r = 0; r < 2; r++) {
            int f   = tid + r * 256;           // 0..511
            int row = f >> 2;                  // 0..127
            int c4  = (f & 3) << 2;            // 0,4,8,12
            float4 va = *(const float4*)(Ab + (size_t)row * K + kt + c4);
            As[c4+0][row] = va.x; As[c4+1][row] = va.y;
            As[c4+2][row] = va.z; As[c4+3][row] = va.w;
            float4 vb = *(const float4*)(Bb + (size_t)row * K + kt + c4);
            Bs[c4+0][row] = vb.x; Bs[c4+1][row] = vb.y;
            Bs[c4+2][row] = vb.z; Bs[c4+3][row] = vb.w;
        }
        __syncthreads();
#pragma unroll
        for (int kk = 0; kk < 16; kk++) {
            float a[8], b[8];
            *(float4*)&a[0] = *(const float4*)&As[kk][ty*8];
            *(float4*)&a[4] = *(const float4*)&As[kk][ty*8+4];
            *(float4*)&b[0] = *(const float4*)&Bs[kk][tx*8];
            *(float4*)&b[4] = *(const float4*)&Bs[kk][tx*8+4];
#pragma unroll
            for (int i = 0; i < 8; i++)
#pragma unroll
                for (int j = 0; j < 8; j++) acc[i][j] += a[i] * b[j];
        }
        __syncthreads();
    }
#pragma unroll
    for (int i = 0; i < 8; i++) {
        size_t row = (size_t)blockIdx.y * 128 + ty*8 + i;
#pragma unroll
        for (int j = 0; j < 8; j += 4) {
            int col = blockIdx.x * 128 + tx*8 + j;
            float4 o;
            o.x = alpha * acc[i][j+0] + bias[col+0];
            o.y = alpha * acc[i][j+1] + bias[col+1];
            o.z = alpha * acc[i][j+2] + bias[col+2];
            o.w = alpha * acc[i][j+3] + bias[col+3];
            *(float4*)(C + row * (size_t)N + col) = o;
        }
    }
}

// ---------------- argmin (reference-exact rounding) + gather + mse -----------
__global__ void argmin_kernel(const float* __restrict__ codebook,
                              float* __restrict__ dout) {
    int wid = threadIdx.x >> 5, lane = threadIdx.x & 31;
    int row = blockIdx.x * 8 + wid;
    __shared__ float part[8];
    __shared__ float cn_s[Sn];
    if (threadIdx.x < Sn) cn_s[threadIdx.x] = g_cnorm[threadIdx.x];
    __syncthreads();

    const float rn = g_rnorm[row];
    float bv = 3.4e38f; int bi = 0;
#pragma unroll
    for (int j = 0; j < 8; j++) {
        int i = j * 32 + lane;                   // ascending per lane
        float dot2 = g_dots[(size_t)row * Sn + i];         // = 2 * f.c_i
        float v = __fadd_rn(__fsub_rn(rn, dot2), cn_s[i]); // (A-B)+C, no FMA
        if (v < bv) { bv = v; bi = i; }          // first min per lane
    }
#pragma unroll
    for (int off = 16; off; off >>= 1) {
        float ov = __shfl_xor_sync(0xffffffffu, bv, off);
        int   oi = __shfl_xor_sync(0xffffffffu, bi, off);
        if (ov < bv || (ov == bv && oi < bi)) { bv = ov; bi = oi; }
    }
    if (lane == 0) {
        g_idx[row] = bi;
        dout[IOFF + row] = (float)bi;
        part[wid] = bv;                          // ||f - c*||^2 (quantized)
    }
    const float4* c4 = (const float4*)(codebook + (size_t)bi * Dn);
    float4* o4 = (float4*)(dout + (size_t)row * Dn);
#pragma unroll
    for (int j = 0; j < 8; j++) o4[j*32 + lane] = __ldg(c4 + j*32 + lane);

    __syncthreads();
    if (threadIdx.x == 0) {
        float s = 0.f;
#pragma unroll
        for (int w = 0; w < 8; w++) s += part[w];
        g_mse_arr[blockIdx.x] = s;
    }
}

// ---------------- persistent GRU recurrence (14 warps, split-k x2) -----------
__device__ __forceinline__ unsigned ld_acquire_u32(const unsigned* p) {
    unsigned v;
    asm volatile("ld.acquire.gpu.u32 %0, [%1];" : "=r"(v) : "l"(p) : "memory");
    return v;
}

__global__ __launch_bounds__(GRU_THREADS, 1)
void gru_kernel(const float* __restrict__ W_hh, const float* __restrict__ b_hh)
{
    extern __shared__ float sh[];           // h[32][HS_PITCH] | codes[32] | part
    int*   codes_s = (int*)(sh + SM_CODES);
    float* part_s  = sh + SM_PART;          // [DPC][3][32]
    const int tid  = threadIdx.x;
    const int wid  = tid >> 5, lane = tid & 31;
    const int p    = wid >> 1;              // 0..6  (d within CTA)
    const int half = wid & 1;               // k-half
    const int d    = blockIdx.x * DPC + p;
    const bool active = (d < Dn);

    float bh_r = 0.f, bh_z = 0.f, bh_n = 0.f;
    const float4 *wr4 = 0, *wz4 = 0, *wn4 = 0;
    if (active) {
        bh_r = b_hh[d]; bh_z = b_hh[Dn + d]; bh_n = b_hh[2*Dn + d];
        int koff = half * 128;              // float4 offset into the row
        wr4 = (const float4*)(W_hh + (size_t)d        * Dn) + koff;
        wz4 = (const float4*)(W_hh + (size_t)(Dn + d) * Dn) + koff;
        wn4 = (const float4*)(W_hh + (size_t)(2*Dn+d) * Dn) + koff;
    }

    for (int t = 0; t < Tn; t++) {
        const float4* hin4 = (const float4*)g_hT[t & 1];
        float*        hout = g_hT[(t + 1) & 1];

        // stage full h (32x1024 f32) into smem via L2-only loads (.cg)
        for (int i = tid; i < (Bn*Dn)/4; i += GRU_THREADS) {
            int b  = i >> 8;                 // 256 float4 per batch row
            int kf = i & 255;
            float4 v = __ldcg(hin4 + i);
            *(float4*)(sh + b * HS_PITCH + kf * 4) = v;
        }
        if (tid < Bn) codes_s[tid] = g_idx[tid * Tn + t];
        __syncthreads();

        float ar = 0.f, az = 0.f, an = 0.f;
        if (active) {
            const float4* hrow =
                (const float4*)(sh + lane * HS_PITCH) + half * 128;
            float ar0=0.f, ar1=0.f, az0=0.f, az1=0.f, an0=0.f, an1=0.f;
#pragma unroll 4
            for (int q = 0; q < 128; q++) {
                float4 h4 = hrow[q];              // LDS.128, conflict-free
                float4 w1 = __ldg(wr4 + q);       // uniform LDG.128, L1-hit
                float4 w2 = __ldg(wz4 + q);
                float4 w3 = __ldg(wn4 + q);
                ar0 += w1.x*h4.x + w1.y*h4.y;  ar1 += w1.z*h4.z + w1.w*h4.w;
                az0 += w2.x*h4.x + w2.y*h4.y;  az1 += w2.z*h4.z + w2.w*h4.w;
                an0 += w3.x*h4.x + w3.y*h4.y;  an1 += w3.z*h4.z + w3.w*h4.w;
            }
            ar = ar0 + ar1; az = az0 + az1; an = an0 + an1;
        }

        float gir = 0.f, giz = 0.f, gin = 0.f;
        if (active && half == 0) {               // only the combiner needs GI
            int code = codes_s[lane];
            const float* gi = g_GI + (size_t)code * (3*Dn);
            gir = __ldcg(gi + d);
            giz = __ldcg(gi + Dn + d);
            gin = __ldcg(gi + 2*Dn + d);
        }
        if (active && half == 1) {               // publish upper-half partials
            part_s[(p*3+0)*32 + lane] = ar;
            part_s[(p*3+1)*32 + lane] = az;
            part_s[(p*3+2)*32 + lane] = an;
        }
        __syncthreads();
        if (active && half == 0) {
            ar += part_s[(p*3+0)*32 + lane];
            az += part_s[(p*3+1)*32 + lane];
            an += part_s[(p*3+2)*32 + lane];
            float r = 1.f / (1.f + expf(-(ar + bh_r + gir)));
            float z = 1.f / (1.f + expf(-(az + bh_z + giz)));
            float n = tanhf(gin + r * (an + bh_n));
            float hprev = sh[lane * HS_PITCH + d];
            float hnew  = (1.f - z) * n + z * hprev;
            hout[lane * Dn + d] = hnew;
            g_H[((size_t)t * Bn + lane) * Dn + d] = hnew;
        }
        __threadfence();
        __syncthreads();
        if (tid == 0) {
            atomicAdd(&g_bar, 1u);
            unsigned target = (unsigned)GRU_CTAS * (unsigned)(t + 1);
            while (ld_acquire_u32(&g_bar) < target) { }
        }
        __syncthreads();
    }
}

// ---------------- CP loss per (k,t): -log(mean_b sigmoid(Hp.(fpos-fneg))) ----
__global__ void cploss_kernel(const float* __restrict__ features,
                              const int* __restrict__ neg_idx)
{
    int t  = blockIdx.x;            // 0..Tn-2
    int kf = blockIdx.y;            // 0..KF-1
    int k  = kf + 1;
    int slot = kf * (Tn - 1) + t;
    if (t >= Tn - k) { if (threadIdx.x == 0) g_cp_arr[slot] = 0.f; return; }

    __shared__ float sig_s[Bn];
    int wid = threadIdx.x >> 5, lane = threadIdx.x & 31;
#pragma unroll
    for (int bi = 0; bi < 4; bi++) {
        int b = wid * 4 + bi;
        const float4* hp = (const float4*)(g_Hp + ((size_t)t * Bn + b) * Dn);
        const float4* fp = (const float4*)(features + ((size_t)b * Tn + (t + k)) * Dn);
        int bneg = neg_idx[((size_t)kf * Tn + t) * Bn + b];
        const float4* fn = (const float4*)(features + ((size_t)bneg * Tn + t) * Dn);
        float s = 0.f;
#pragma unroll
        for (int j = 0; j < 8; j++) {
            float4 h4 = hp[j*32 + lane];
            float4 p4 = fp[j*32 + lane];
            float4 n4 = fn[j*32 + lane];
            s += h4.x*(p4.x-n4.x) + h4.y*(p4.y-n4.y)
               + h4.z*(p4.z-n4.z) + h4.w*(p4.w-n4.w);
        }
#pragma unroll
        for (int off = 16; off; off >>= 1) s += __shfl_xor_sync(0xffffffffu, s, off);
        if (lane == 0) sig_s[b] = 1.f / (1.f + expf(-s));
    }
    __syncthreads();
    if (threadIdx.x == 0) {
        float m = 0.f;
#pragma unroll
        for (int b = 0; b < Bn; b++) m += sig_s[b];
        g_cp_arr[slot] = -logf(m * (1.f / (float)Bn));
    }
}

// ---------------- final deterministic reduction -------------------------------
__global__ void finalize_kernel(float* __restrict__ dout) {
    __shared__ float red[256];
    int tid = threadIdx.x;
    float s = 0.f;
    for (int i = tid; i < KF*(Tn-1); i += 256) s += g_cp_arr[i];
    red[tid] = s; __syncthreads();
    for (int o = 128; o; o >>= 1) { if (tid < o) red[tid] += red[tid+o]; __syncthreads(); }
    float cp = red[0]; __syncthreads();
    float m = 0.f;
    for (int i = tid; i < Mrows/8; i += 256) m += g_mse_arr[i];
    red[tid] = m; __syncthreads();
    for (int o = 128; o; o >>= 1) { if (tid < o) red[tid] += red[tid+o]; __syncthreads(); }
    if (tid == 0) {
        float mse = red[0] / ((float)Mrows * (float)Dn);
        // commitment == codebook loss numerically -> 1.25 * mse
        dout[LOFF] = cp / (float)(KF * (Tn - KF)) + 1.25f * mse;
    }
}

// ---------------- launch --------------------------------------------------------
extern "C" void kernel_launch(void* const* d_in, const int* in_sizes, int n_in,
                              void* d_out, int out_size) {
    (void)in_sizes; (void)n_in; (void)out_size;
    const float* features = (const float*)d_in[0];
    const float* codebook = (const float*)d_in[1];
    const float* W_ih     = (const float*)d_in[2];
    const float* W_hh     = (const float*)d_in[3];
    const float* b_ih     = (const float*)d_in[4];
    const float* b_hh     = (const float*)d_in[5];
    const float* W_p      = (const float*)d_in[6];
    const float* b_p      = (const float*)d_in[7];
    const int*   neg_idx  = (const int*)d_in[8];
    float* dout = (float*)d_out;

    void *p_rnorm, *p_cnorm, *p_dots, *p_GI, *p_H, *p_Hp, *p_zb;
    cudaGetSymbolAddress(&p_rnorm, g_rnorm);
    cudaGetSymbolAddress(&p_cnorm, g_cnorm);
    cudaGetSymbolAddress(&p_dots,  g_dots);
    cudaGetSymbolAddress(&p_GI,    g_GI);
    cudaGetSymbolAddress(&p_H,     g_H);
    cudaGetSymbolAddress(&p_Hp,    g_Hp);
    cudaGetSymbolAddress(&p_zb,    g_zbias);

    cudaFuncSetAttribute(gru_kernel,
        cudaFuncAttributeMaxDynamicSharedMemorySize, GRU_SMEM);

    init_kernel<<<(Bn*Dn + 255)/256, 256>>>();

    rownorm_kernel<<<Mrows/8, 256>>>(features, (float*)p_rnorm, Mrows);
    rownorm_kernel<<<Sn/8,    256>>>(codebook, (float*)p_cnorm, Sn);

    // dots = 2 * F C^T   (M x S), raw (no bias) so argmin can replicate
    // the reference's (A - B) + C rounding order exactly.
    sgemm_nt<<<dim3(Sn/128, Mrows/128), 256>>>(
        features, codebook, (float*)p_dots, (const float*)p_zb,
        Mrows, Sn, Dn, 2.0f);

    argmin_kernel<<<Mrows/8, 256>>>(codebook, dout);

    // GI = codebook @ W_ih^T + b_ih   (S x 3D)
    sgemm_nt<<<dim3(3*Dn/128, Sn/128), 256>>>(
        codebook, W_ih, (float*)p_GI, b_ih, Sn, 3*Dn, Dn, 1.0f);

    gru_kernel<<<GRU_CTAS, GRU_THREADS, GRU_SMEM>>>(W_hh, b_hh);

    // Hp = H @ W_p^T + b_p   (M x D)
    sgemm_nt<<<dim3(Dn/128, Mrows/128), 256>>>(
        (const float*)p_H, W_p, (float*)p_Hp, b_p, Mrows, Dn, Dn, 1.0f);

    cploss_kernel<<<dim3(Tn-1, KF), 256>>>(features, neg_idx);

    finalize_kernel<<<1, 256>>>(dout);
}

// round 10
// speedup vs baseline: 1.3744x; 1.0510x over previous
#include <cuda_runtime.h>
#include <math.h>
#include <stdint.h>
#include <stddef.h>

// ---------------- problem constants ----------------
#define Bn   32
#define Tn   1024
#define Dn   1024
#define Sn   256
#define KF   3
#define Mrows (Bn*Tn)                 // 32768
#define IOFF  ((size_t)Bn*Tn*Dn)      // 33554432 (indices start in d_out)
#define LOFF  (IOFF + (size_t)Bn*Tn)  // total scalar slot

#define GRU_CTAS    147
#define DPC         7                 // d-columns per CTA (147*7 = 1029 >= 1024)
#define NQ          4                 // split-k quarters per d-column
#define GRU_WARPS   (DPC*NQ)          // 28
#define GRU_THREADS (GRU_WARPS*32)    // 896
#define HS_PITCH    1028              // %32==4 -> conflict-free LDS.128 phases
#define SM_CODES    (32*HS_PITCH)                 // float offset of codes[32]
#define SM_PART     (SM_CODES + 32)               // part[DPC][3][NQ-1][32]
#define GRU_SMEM    ((SM_PART + DPC*3*(NQ-1)*32)*4)

// ---------------- device scratch (no allocations) ----------------
__device__ float g_dots[(size_t)Mrows * Sn];   // 33.5 MB : 2*F.C^T
__device__ float g_H  [(size_t)Mrows * Dn];    // 134 MB, row = t*Bn + b
__device__ float g_Hp [(size_t)Mrows * Dn];    // 134 MB, same layout
__device__ float g_GI [(size_t)Sn * 3*Dn];     // 3 MB
__device__ float g_hT [2][Bn * Dn];            // double-buffered h, [b][k]
__device__ float g_rnorm[Mrows];
__device__ float g_cnorm[Sn];
__device__ float g_zbias[Sn];                  // zero-initialized, never written
__device__ int   g_idx[Mrows];                 // row = b*Tn + t
__device__ float g_mse_arr[Mrows/8];           // 4096 per-block partials
__device__ float g_cp_arr[KF*(Tn-1)];          // 3069 slots
__device__ unsigned g_bar;

// ---------------- launch #1: rownorms (features+codebook) + init -------------
// blocks [0,4096): feature rows; [4096,4128): codebook rows;
// [4128,4256): zero g_hT[0]; last block thread0 resets g_bar.
__global__ void prep_kernel(const float* __restrict__ features,
                            const float* __restrict__ codebook) {
    int bx = blockIdx.x;
    if (bx < 4096 + 32) {
        const float* X = (bx < 4096) ? features : codebook;
        float* out     = (bx < 4096) ? g_rnorm : g_cnorm;
        int base       = (bx < 4096) ? bx * 8 : (bx - 4096) * 8;
        int wid = threadIdx.x >> 5, lane = threadIdx.x & 31;
        int row = base + wid;
        const float4* x = (const float4*)(X + (size_t)row * Dn);
        float s = 0.f;
#pragma unroll
        for (int j = 0; j < 8; j++) {
            float4 v = x[j*32 + lane];
            s += v.x*v.x + v.y*v.y + v.z*v.z + v.w*v.w;
        }
#pragma unroll
        for (int off = 16; off; off >>= 1) s += __shfl_xor_sync(0xffffffffu, s, off);
        if (lane == 0) out[row] = s;
    } else {
        int i = (bx - 4128) * 256 + threadIdx.x;
        if (i < Bn*Dn) g_hT[0][i] = 0.f;
        if (bx == gridDim.x - 1 && threadIdx.x == 0) g_bar = 0u;
    }
}

// ---------------- launch #2: fused SGEMM (dots + GI in one grid) --------------
// C = alpha*A*B^T + bias[col]; identical FFMA chain to the proven kernel, so
// the dots result (and hence argmin/indices) is bit-identical.
#define DOTS_BLKS 512                  // dots: (2 x 256) tiles
__global__ __launch_bounds__(256, 2)
void sgemm_fused(const float* __restrict__ A1, const float* __restrict__ B1,
                 float* __restrict__ C1, const float* __restrict__ bias1,
                 int K1, float alpha1, int N1,
                 const float* __restrict__ A2, const float* __restrict__ B2,
                 float* __restrict__ C2, const float* __restrict__ bias2,
                 int K2, float alpha2, int N2)
{
    __shared__ float As[16][128];
    __shared__ float Bs[16][128];
    const int tid = threadIdx.x;
    const int tx = tid & 15, ty = tid >> 4;

    const float *A, *Bm, *bias; float *C;
    int K, N, bxn, byn; float alpha;
    if (blockIdx.x < DOTS_BLKS) {
        A = A1; Bm = B1; C = C1; bias = bias1; K = K1; N = N1; alpha = alpha1;
        bxn = blockIdx.x & 1;  byn = blockIdx.x >> 1;      // (2, 256)
    } else {
        int i = blockIdx.x - DOTS_BLKS;
        A = A2; Bm = B2; C = C2; bias = bias2; K = K2; N = N2; alpha = alpha2;
        bxn = i % 24;          byn = i / 24;               // (24, 2)
    }
    const float* Ab = A  + (size_t)byn * 128 * K;
    const float* Bb = Bm + (size_t)bxn * 128 * K;

    float acc[8][8];
#pragma unroll
    for (int i = 0; i < 8; i++)
#pragma unroll
        for (int j = 0; j < 8; j++) acc[i][j] = 0.f;

    for (int kt = 0; kt < K; kt += 16) {
#pragma unroll
        for (int r = 0; r < 2; r++) {
            int f   = tid + r * 256;
            int row = f >> 2;
            int c4  = (f & 3) << 2;
            float4 va = *(const float4*)(Ab + (size_t)row * K + kt + c4);
            As[c4+0][row] = va.x; As[c4+1][row] = va.y;
            As[c4+2][row] = va.z; As[c4+3][row] = va.w;
            float4 vb = *(const float4*)(Bb + (size_t)row * K + kt + c4);
            Bs[c4+0][row] = vb.x; Bs[c4+1][row] = vb.y;
            Bs[c4+2][row] = vb.z; Bs[c4+3][row] = vb.w;
        }
        __syncthreads();
#pragma unroll
        for (int kk = 0; kk < 16; kk++) {
            float a[8], b[8];
            *(float4*)&a[0] = *(const float4*)&As[kk][ty*8];
            *(float4*)&a[4] = *(const float4*)&As[kk][ty*8+4];
            *(float4*)&b[0] = *(const float4*)&Bs[kk][tx*8];
            *(float4*)&b[4] = *(const float4*)&Bs[kk][tx*8+4];
#pragma unroll
            for (int i = 0; i < 8; i++)
#pragma unroll
                for (int j = 0; j < 8; j++) acc[i][j] += a[i] * b[j];
        }
        __syncthreads();
    }
#pragma unroll
    for (int i = 0; i < 8; i++) {
        size_t row = (size_t)byn * 128 + ty*8 + i;
#pragma unroll
        for (int j = 0; j < 8; j += 4) {
            int col = bxn * 128 + tx*8 + j;
            float4 o;
            o.x = alpha * acc[i][j+0] + bias[col+0];
            o.y = alpha * acc[i][j+1] + bias[col+1];
            o.z = alpha * acc[i][j+2] + bias[col+2];
            o.w = alpha * acc[i][j+3] + bias[col+3];
            *(float4*)(C + row * (size_t)N + col) = o;
        }
    }
}

// ---------------- plain SGEMM (Hp) — proven fp32-roofline version ------------
__global__ __launch_bounds__(256, 2)
void sgemm_nt(const float* __restrict__ A, const float* __restrict__ Bm,
              float* __restrict__ C, const float* __restrict__ bias,
              int M, int N, int K, float alpha)
{
    __shared__ float As[16][128];
    __shared__ float Bs[16][128];
    const int tid = threadIdx.x;
    const int tx = tid & 15, ty = tid >> 4;
    const float* Ab = A + (size_t)blockIdx.y * 128 * K;
    const float* Bb = Bm + (size_t)blockIdx.x * 128 * K;

    float acc[8][8];
#pragma unroll
    for (int i = 0; i < 8; i++)
#pragma unroll
        for (int j = 0; j < 8; j++) acc[i][j] = 0.f;

    for (int kt = 0; kt < K; kt += 16) {
#pragma unroll
        for (int r = 0; r < 2; r++) {
            int f   = tid + r * 256;
            int row = f >> 2;
            int c4  = (f & 3) << 2;
            float4 va = *(const float4*)(Ab + (size_t)row * K + kt + c4);
            As[c4+0][row] = va.x; As[c4+1][row] = va.y;
            As[c4+2][row] = va.z; As[c4+3][row] = va.w;
            float4 vb = *(const float4*)(Bb + (size_t)row * K + kt + c4);
            Bs[c4+0][row] = vb.x; Bs[c4+1][row] = vb.y;
            Bs[c4+2][row] = vb.z; Bs[c4+3][row] = vb.w;
        }
        __syncthreads();
#pragma unroll
        for (int kk = 0; kk < 16; kk++) {
            float a[8], b[8];
            *(float4*)&a[0] = *(const float4*)&As[kk][ty*8];
            *(float4*)&a[4] = *(const float4*)&As[kk][ty*8+4];
            *(float4*)&b[0] = *(const float4*)&Bs[kk][tx*8];
            *(float4*)&b[4] = *(const float4*)&Bs[kk][tx*8+4];
#pragma unroll
            for (int i = 0; i < 8; i++)
#pragma unroll
                for (int j = 0; j < 8; j++) acc[i][j] += a[i] * b[j];
        }
        __syncthreads();
    }
#pragma unroll
    for (int i = 0; i < 8; i++) {
        size_t row = (size_t)blockIdx.y * 128 + ty*8 + i;
#pragma unroll
        for (int j = 0; j < 8; j += 4) {
            int col = blockIdx.x * 128 + tx*8 + j;
            float4 o;
            o.x = alpha * acc[i][j+0] + bias[col+0];
            o.y = alpha * acc[i][j+1] + bias[col+1];
            o.z = alpha * acc[i][j+2] + bias[col+2];
            o.w = alpha * acc[i][j+3] + bias[col+3];
            *(float4*)(C + row * (size_t)N + col) = o;
        }
    }
}

// ---------------- launch #3: argmin (reference-exact) + gather + mse ---------
__global__ void argmin_kernel(const float* __restrict__ codebook,
                              float* __restrict__ dout) {
    int wid = threadIdx.x >> 5, lane = threadIdx.x & 31;
    int row = blockIdx.x * 8 + wid;
    __shared__ float part[8];
    __shared__ float cn_s[Sn];
    if (threadIdx.x < Sn) cn_s[threadIdx.x] = g_cnorm[threadIdx.x];
    __syncthreads();

    const float rn = g_rnorm[row];
    float bv = 3.4e38f; int bi = 0;
#pragma unroll
    for (int j = 0; j < 8; j++) {
        int i = j * 32 + lane;                   // ascending per lane
        float dot2 = g_dots[(size_t)row * Sn + i];         // = 2 * f.c_i
        float v = __fadd_rn(__fsub_rn(rn, dot2), cn_s[i]); // (A-B)+C, no FMA
        if (v < bv) { bv = v; bi = i; }          // first min per lane
    }
#pragma unroll
    for (int off = 16; off; off >>= 1) {
        float ov = __shfl_xor_sync(0xffffffffu, bv, off);
        int   oi = __shfl_xor_sync(0xffffffffu, bi, off);
        if (ov < bv || (ov == bv && oi < bi)) { bv = ov; bi = oi; }
    }
    if (lane == 0) {
        g_idx[row] = bi;
        dout[IOFF + row] = (float)bi;
        part[wid] = bv;                          // ||f - c*||^2 (quantized)
    }
    const float4* c4 = (const float4*)(codebook + (size_t)bi * Dn);
    float4* o4 = (float4*)(dout + (size_t)row * Dn);
#pragma unroll
    for (int j = 0; j < 8; j++) o4[j*32 + lane] = __ldg(c4 + j*32 + lane);

    __syncthreads();
    if (threadIdx.x == 0) {
        float s = 0.f;
#pragma unroll
        for (int w = 0; w < 8; w++) s += part[w];
        g_mse_arr[blockIdx.x] = s;
    }
}

// ---------------- launch #4 (profiled slot): persistent GRU ------------------
// 28 warps: warp = (p, quarter); d = bid*7+p, k-range = quarter*256 + [0,256).
// Barrier: CG-style — bar.sync, then fence+atomic+spin by tid0 only.
__device__ __forceinline__ unsigned ld_acquire_u32(const unsigned* p) {
    unsigned v;
    asm volatile("ld.acquire.gpu.u32 %0, [%1];" : "=r"(v) : "l"(p) : "memory");
    return v;
}

__global__ __launch_bounds__(GRU_THREADS, 1)
void gru_kernel(const float* __restrict__ W_hh, const float* __restrict__ b_hh)
{
    extern __shared__ float sh[];          // h[32][HS_PITCH] | codes | parts
    int*   codes_s = (int*)(sh + SM_CODES);
    float* part_s  = sh + SM_PART;         // [DPC][3][NQ-1][32]
    const int tid  = threadIdx.x;
    const int wid  = tid >> 5, lane = tid & 31;
    const int p    = wid >> 2;             // 0..6  (d within CTA)
    const int qtr  = wid & 3;              // k-quarter
    const int d    = blockIdx.x * DPC + p;
    const bool active = (d < Dn);

    float bh_r = 0.f, bh_z = 0.f, bh_n = 0.f;
    const float4 *wr4 = 0, *wz4 = 0, *wn4 = 0;
    if (active) {
        bh_r = b_hh[d]; bh_z = b_hh[Dn + d]; bh_n = b_hh[2*Dn + d];
        int koff = qtr * 64;               // float4 offset into the row
        wr4 = (const float4*)(W_hh + (size_t)d        * Dn) + koff;
        wz4 = (const float4*)(W_hh + (size_t)(Dn + d) * Dn) + koff;
        wn4 = (const float4*)(W_hh + (size_t)(2*Dn+d) * Dn) + koff;
    }

    for (int t = 0; t < Tn; t++) {
        const float4* hin4 = (const float4*)g_hT[t & 1];
        float*        hout = g_hT[(t + 1) & 1];

        // stage full h (32x1024 f32) into smem via L2-only loads (.cg)
        for (int i = tid; i < (Bn*Dn)/4; i += GRU_THREADS) {
            int b  = i >> 8;               // 256 float4 per batch row
            int kf = i & 255;
            float4 v = __ldcg(hin4 + i);
            *(float4*)(sh + b * HS_PITCH + kf * 4) = v;
        }
        if (tid < Bn) codes_s[tid] = g_idx[tid * Tn + t];
        __syncthreads();

        // GI prefetch (combiner warps only) — overlaps with dot loop
        float gir = 0.f, giz = 0.f, gin = 0.f;
        if (active && qtr == 0) {
            int code = codes_s[lane];
            const float* gi = g_GI + (size_t)code * (3*Dn);
            gir = __ldcg(gi + d);
            giz = __ldcg(gi + Dn + d);
            gin = __ldcg(gi + 2*Dn + d);
        }

        float ar = 0.f, az = 0.f, an = 0.f;
        if (active) {
            const float4* hrow =
                (const float4*)(sh + lane * HS_PITCH) + qtr * 64;
            float ar0=0.f, ar1=0.f, az0=0.f, az1=0.f, an0=0.f, an1=0.f;
#pragma unroll 4
            for (int q = 0; q < 64; q++) {
                float4 h4 = hrow[q];              // LDS.128, conflict-free
                float4 w1 = __ldg(wr4 + q);       // uniform LDG.128, L1-hit
                float4 w2 = __ldg(wz4 + q);
                float4 w3 = __ldg(wn4 + q);
                ar0 += w1.x*h4.x + w1.y*h4.y;  ar1 += w1.z*h4.z + w1.w*h4.w;
                az0 += w2.x*h4.x + w2.y*h4.y;  az1 += w2.z*h4.z + w2.w*h4.w;
                an0 += w3.x*h4.x + w3.y*h4.y;  an1 += w3.z*h4.z + w3.w*h4.w;
            }
            ar = ar0 + ar1; az = az0 + az1; an = an0 + an1;
        }

        if (active && qtr != 0) {              // publish partials
            int base = ((p*3)*(NQ-1) + (qtr-1))*32 + lane;
            part_s[base                 ] = ar;
            part_s[base + (NQ-1)*32     ] = az;
            part_s[base + 2*(NQ-1)*32   ] = an;
        }
        __syncthreads();
        if (active && qtr == 0) {
            int base = (p*3)*(NQ-1)*32 + lane;
#pragma unroll
            for (int qq = 0; qq < NQ-1; qq++) {
                ar += part_s[base + qq*32                   ];
                az += part_s[base + qq*32 + (NQ-1)*32       ];
                an += part_s[base + qq*32 + 2*(NQ-1)*32     ];
            }
            float r = 1.f / (1.f + expf(-(ar + bh_r + gir)));
            float z = 1.f / (1.f + expf(-(az + bh_z + giz)));
            float n = tanhf(gin + r * (an + bh_n));
            float hprev = sh[lane * HS_PITCH + d];
            float hnew  = (1.f - z) * n + z * hprev;
            hout[lane * Dn + d] = hnew;
            g_H[((size_t)t * Bn + lane) * Dn + d] = hnew;
        }
        __syncthreads();
        if (tid == 0) {
            __threadfence();                   // cumulative: covers all CTA stores
            atomicAdd(&g_bar, 1u);
            unsigned target = (unsigned)GRU_CTAS * (unsigned)(t + 1);
            while (ld_acquire_u32(&g_bar) < target) { }
        }
        __syncthreads();
    }
}

// ---------------- CP loss per (k,t) ------------------------------------------
__global__ void cploss_kernel(const float* __restrict__ features,
                              const int* __restrict__ neg_idx)
{
    int t  = blockIdx.x;            // 0..Tn-2
    int kf = blockIdx.y;            // 0..KF-1
    int k  = kf + 1;
    int slot = kf * (Tn - 1) + t;
    if (t >= Tn - k) { if (threadIdx.x == 0) g_cp_arr[slot] = 0.f; return; }

    __shared__ float sig_s[Bn];
    int wid = threadIdx.x >> 5, lane = threadIdx.x & 31;
#pragma unroll
    for (int bi = 0; bi < 4; bi++) {
        int b = wid * 4 + bi;
        const float4* hp = (const float4*)(g_Hp + ((size_t)t * Bn + b) * Dn);
        const float4* fp = (const float4*)(features + ((size_t)b * Tn + (t + k)) * Dn);
        int bneg = neg_idx[((size_t)kf * Tn + t) * Bn + b];
        const float4* fn = (const float4*)(features + ((size_t)bneg * Tn + t) * Dn);
        float s = 0.f;
#pragma unroll
        for (int j = 0; j < 8; j++) {
            float4 h4 = hp[j*32 + lane];
            float4 p4 = fp[j*32 + lane];
            float4 n4 = fn[j*32 + lane];
            s += h4.x*(p4.x-n4.x) + h4.y*(p4.y-n4.y)
               + h4.z*(p4.z-n4.z) + h4.w*(p4.w-n4.w);
        }
#pragma unroll
        for (int off = 16; off; off >>= 1) s += __shfl_xor_sync(0xffffffffu, s, off);
        if (lane == 0) sig_s[b] = 1.f / (1.f + expf(-s));
    }
    __syncthreads();
    if (threadIdx.x == 0) {
        float m = 0.f;
#pragma unroll
        for (int b = 0; b < Bn; b++) m += sig_s[b];
        g_cp_arr[slot] = -logf(m * (1.f / (float)Bn));
    }
}

// ---------------- final deterministic reduction -------------------------------
__global__ void finalize_kernel(float* __restrict__ dout) {
    __shared__ float red[256];
    int tid = threadIdx.x;
    float s = 0.f;
    for (int i = tid; i < KF*(Tn-1); i += 256) s += g_cp_arr[i];
    red[tid] = s; __syncthreads();
    for (int o = 128; o; o >>= 1) { if (tid < o) red[tid] += red[tid+o]; __syncthreads(); }
    float cp = red[0]; __syncthreads();
    float m = 0.f;
    for (int i = tid; i < Mrows/8; i += 256) m += g_mse_arr[i];
    red[tid] = m; __syncthreads();
    for (int o = 128; o; o >>= 1) { if (tid < o) red[tid] += red[tid+o]; __syncthreads(); }
    if (tid == 0) {
        float mse = red[0] / ((float)Mrows * (float)Dn);
        dout[LOFF] = cp / (float)(KF * (Tn - KF)) + 1.25f * mse;
    }
}

// ---------------- launch --------------------------------------------------------
extern "C" void kernel_launch(void* const* d_in, const int* in_sizes, int n_in,
                              void* d_out, int out_size) {
    (void)in_sizes; (void)n_in; (void)out_size;
    const float* features = (const float*)d_in[0];
    const float* codebook = (const float*)d_in[1];
    const float* W_ih     = (const float*)d_in[2];
    const float* W_hh     = (const float*)d_in[3];
    const float* b_ih     = (const float*)d_in[4];
    const float* b_hh     = (const float*)d_in[5];
    const float* W_p      = (const float*)d_in[6];
    const float* b_p      = (const float*)d_in[7];
    const int*   neg_idx  = (const int*)d_in[8];
    float* dout = (float*)d_out;

    void *p_dots, *p_GI, *p_H, *p_Hp, *p_zb;
    cudaGetSymbolAddress(&p_dots,  g_dots);
    cudaGetSymbolAddress(&p_GI,    g_GI);
    cudaGetSymbolAddress(&p_H,     g_H);
    cudaGetSymbolAddress(&p_Hp,    g_Hp);
    cudaGetSymbolAddress(&p_zb,    g_zbias);

    cudaFuncSetAttribute(gru_kernel,
        cudaFuncAttributeMaxDynamicSharedMemorySize, GRU_SMEM);

    // #1: rownorms + h0/bar init
    prep_kernel<<<4096 + 32 + 128, 256>>>(features, codebook);

    // #2: fused GEMM — dots = 2*F C^T (bit-identical chain) and
    //                  GI = codebook @ W_ih^T + b_ih
    sgemm_fused<<<DOTS_BLKS + 48, 256>>>(
        features, codebook, (float*)p_dots, (const float*)p_zb, Dn, 2.0f, Sn,
        codebook, W_ih,     (float*)p_GI,   b_ih,               Dn, 1.0f, 3*Dn);

    // #3: argmin + quantized gather + mse partials
    argmin_kernel<<<Mrows/8, 256>>>(codebook, dout);

    // #4 (profiled): persistent GRU recurrence
    gru_kernel<<<GRU_CTAS, GRU_THREADS, GRU_SMEM>>>(W_hh, b_hh);

    // #5: Hp = H @ W_p^T + b_p
    sgemm_nt<<<dim3(Dn/128, Mrows/128), 256>>>(
        (const float*)p_H, W_p, (float*)p_Hp, b_p, Mrows, Dn, Dn, 1.0f);

    // #6: CP loss terms
    cploss_kernel<<<dim3(Tn-1, KF), 256>>>(features, neg_idx);

    // #7: deterministic final reduction
    finalize_kernel<<<1, 256>>>(dout);
}

// round 11
// speedup vs baseline: 1.7500x; 1.2733x over previous
#include <cuda_runtime.h>
#include <math.h>
#include <stdint.h>
#include <stddef.h>

// ---------------- problem constants ----------------
#define Bn   32
#define Tn   1024
#define Dn   1024
#define Sn   256
#define KF   3
#define Mrows (Bn*Tn)                 // 32768
#define IOFF  ((size_t)Bn*Tn*Dn)      // 33554432 (indices start in d_out)
#define LOFF  (IOFF + (size_t)Bn*Tn)  // total scalar slot

#define GRU_CTAS    147
#define DPC         7                 // d-columns per CTA (147*7 = 1029 >= 1024)
#define NW          16                // warps = k-segments of 64
#define GRU_THREADS (NW*32)           // 512
#define KSEG        (Dn/NW)           // 64

// ---------------- device scratch (no allocations) ----------------
__device__ float g_dots[(size_t)Mrows * Sn];   // 33.5 MB : 2*F.C^T
__device__ float g_H  [(size_t)Mrows * Dn];    // 134 MB, row = t*Bn + b
__device__ float g_Hp [(size_t)Mrows * Dn];    // 134 MB, same layout
__device__ float g_GI [(size_t)Sn * 3*Dn];     // 3 MB
__device__ float g_hT2[2][Dn*Bn];              // double-buffered h, [k][b]
__device__ float g_rnorm[Mrows];
__device__ float g_cnorm[Sn];
__device__ float g_zbias[Sn];                  // zero-initialized, never written
__device__ int   g_idx[Mrows];                 // row = b*Tn + t
__device__ float g_mse_arr[Mrows/8];           // 4096 per-block partials
__device__ float g_cp_arr[KF*(Tn-1)];          // 3069 slots
__device__ unsigned g_bar;

// ---------------- launch #1: rownorms + h0/bar init ---------------------------
__global__ void prep_kernel(const float* __restrict__ features,
                            const float* __restrict__ codebook) {
    int bx = blockIdx.x;
    if (bx < 4096 + 32) {
        const float* X = (bx < 4096) ? features : codebook;
        float* out     = (bx < 4096) ? g_rnorm : g_cnorm;
        int base       = (bx < 4096) ? bx * 8 : (bx - 4096) * 8;
        int wid = threadIdx.x >> 5, lane = threadIdx.x & 31;
        int row = base + wid;
        const float4* x = (const float4*)(X + (size_t)row * Dn);
        float s = 0.f;
#pragma unroll
        for (int j = 0; j < 8; j++) {
            float4 v = x[j*32 + lane];
            s += v.x*v.x + v.y*v.y + v.z*v.z + v.w*v.w;
        }
#pragma unroll
        for (int off = 16; off; off >>= 1) s += __shfl_xor_sync(0xffffffffu, s, off);
        if (lane == 0) out[row] = s;
    } else {
        int i = (bx - 4128) * 256 + threadIdx.x;
        if (i < Bn*Dn) g_hT2[0][i] = 0.f;
        if (bx == gridDim.x - 1 && threadIdx.x == 0) g_bar = 0u;
    }
}

// ---------------- launch #2: fused SGEMM (dots + GI) --------------------------
// C = alpha*A*B^T + bias[col]; FFMA chain identical to the proven kernel ->
// dots (hence argmin/indices) bit-identical.
#define DOTS_BLKS 512
__global__ __launch_bounds__(256, 2)
void sgemm_fused(const float* __restrict__ A1, const float* __restrict__ B1,
                 float* __restrict__ C1, const float* __restrict__ bias1,
                 int K1, float alpha1, int N1,
                 const float* __restrict__ A2, const float* __restrict__ B2,
                 float* __restrict__ C2, const float* __restrict__ bias2,
                 int K2, float alpha2, int N2)
{
    __shared__ float As[16][128];
    __shared__ float Bs[16][128];
    const int tid = threadIdx.x;
    const int tx = tid & 15, ty = tid >> 4;

    const float *A, *Bm, *bias; float *C;
    int K, N, bxn, byn; float alpha;
    if (blockIdx.x < DOTS_BLKS) {
        A = A1; Bm = B1; C = C1; bias = bias1; K = K1; N = N1; alpha = alpha1;
        bxn = blockIdx.x & 1;  byn = blockIdx.x >> 1;
    } else {
        int i = blockIdx.x - DOTS_BLKS;
        A = A2; Bm = B2; C = C2; bias = bias2; K = K2; N = N2; alpha = alpha2;
        bxn = i % 24;          byn = i / 24;
    }
    const float* Ab = A  + (size_t)byn * 128 * K;
    const float* Bb = Bm + (size_t)bxn * 128 * K;

    float acc[8][8];
#pragma unroll
    for (int i = 0; i < 8; i++)
#pragma unroll
        for (int j = 0; j < 8; j++) acc[i][j] = 0.f;

    for (int kt = 0; kt < K; kt += 16) {
#pragma unroll
        for (int r = 0; r < 2; r++) {
            int f   = tid + r * 256;
            int row = f >> 2;
            int c4  = (f & 3) << 2;
            float4 va = *(const float4*)(Ab + (size_t)row * K + kt + c4);
            As[c4+0][row] = va.x; As[c4+1][row] = va.y;
            As[c4+2][row] = va.z; As[c4+3][row] = va.w;
            float4 vb = *(const float4*)(Bb + (size_t)row * K + kt + c4);
            Bs[c4+0][row] = vb.x; Bs[c4+1][row] = vb.y;
            Bs[c4+2][row] = vb.z; Bs[c4+3][row] = vb.w;
        }
        __syncthreads();
#pragma unroll
        for (int kk = 0; kk < 16; kk++) {
            float a[8], b[8];
            *(float4*)&a[0] = *(const float4*)&As[kk][ty*8];
            *(float4*)&a[4] = *(const float4*)&As[kk][ty*8+4];
            *(float4*)&b[0] = *(const float4*)&Bs[kk][tx*8];
            *(float4*)&b[4] = *(const float4*)&Bs[kk][tx*8+4];
#pragma unroll
            for (int i = 0; i < 8; i++)
#pragma unroll
                for (int j = 0; j < 8; j++) acc[i][j] += a[i] * b[j];
        }
        __syncthreads();
    }
#pragma unroll
    for (int i = 0; i < 8; i++) {
        size_t row = (size_t)byn * 128 + ty*8 + i;
#pragma unroll
        for (int j = 0; j < 8; j += 4) {
            int col = bxn * 128 + tx*8 + j;
            float4 o;
            o.x = alpha * acc[i][j+0] + bias[col+0];
            o.y = alpha * acc[i][j+1] + bias[col+1];
            o.z = alpha * acc[i][j+2] + bias[col+2];
            o.w = alpha * acc[i][j+3] + bias[col+3];
            *(float4*)(C + row * (size_t)N + col) = o;
        }
    }
}

// ---------------- plain SGEMM (Hp) — proven fp32-roofline version ------------
__global__ __launch_bounds__(256, 2)
void sgemm_nt(const float* __restrict__ A, const float* __restrict__ Bm,
              float* __restrict__ C, const float* __restrict__ bias,
              int M, int N, int K, float alpha)
{
    __shared__ float As[16][128];
    __shared__ float Bs[16][128];
    const int tid = threadIdx.x;
    const int tx = tid & 15, ty = tid >> 4;
    const float* Ab = A + (size_t)blockIdx.y * 128 * K;
    const float* Bb = Bm + (size_t)blockIdx.x * 128 * K;

    float acc[8][8];
#pragma unroll
    for (int i = 0; i < 8; i++)
#pragma unroll
        for (int j = 0; j < 8; j++) acc[i][j] = 0.f;

    for (int kt = 0; kt < K; kt += 16) {
#pragma unroll
        for (int r = 0; r < 2; r++) {
            int f   = tid + r * 256;
            int row = f >> 2;
            int c4  = (f & 3) << 2;
            float4 va = *(const float4*)(Ab + (size_t)row * K + kt + c4);
            As[c4+0][row] = va.x; As[c4+1][row] = va.y;
            As[c4+2][row] = va.z; As[c4+3][row] = va.w;
            float4 vb = *(const float4*)(Bb + (size_t)row * K + kt + c4);
            Bs[c4+0][row] = vb.x; Bs[c4+1][row] = vb.y;
            Bs[c4+2][row] = vb.z; Bs[c4+3][row] = vb.w;
        }
        __syncthreads();
#pragma unroll
        for (int kk = 0; kk < 16; kk++) {
            float a[8], b[8];
            *(float4*)&a[0] = *(const float4*)&As[kk][ty*8];
            *(float4*)&a[4] = *(const float4*)&As[kk][ty*8+4];
            *(float4*)&b[0] = *(const float4*)&Bs[kk][tx*8];
            *(float4*)&b[4] = *(const float4*)&Bs[kk][tx*8+4];
#pragma unroll
            for (int i = 0; i < 8; i++)
#pragma unroll
                for (int j = 0; j < 8; j++) acc[i][j] += a[i] * b[j];
        }
        __syncthreads();
    }
#pragma unroll
    for (int i = 0; i < 8; i++) {
        size_t row = (size_t)blockIdx.y * 128 + ty*8 + i;
#pragma unroll
        for (int j = 0; j < 8; j += 4) {
            int col = blockIdx.x * 128 + tx*8 + j;
            float4 o;
            o.x = alpha * acc[i][j+0] + bias[col+0];
            o.y = alpha * acc[i][j+1] + bias[col+1];
            o.z = alpha * acc[i][j+2] + bias[col+2];
            o.w = alpha * acc[i][j+3] + bias[col+3];
            *(float4*)(C + row * (size_t)N + col) = o;
        }
    }
}

// ---------------- launch #3: argmin (reference-exact) + gather + mse ---------
__global__ void argmin_kernel(const float* __restrict__ codebook,
                              float* __restrict__ dout) {
    int wid = threadIdx.x >> 5, lane = threadIdx.x & 31;
    int row = blockIdx.x * 8 + wid;
    __shared__ float part[8];
    __shared__ float cn_s[Sn];
    if (threadIdx.x < Sn) cn_s[threadIdx.x] = g_cnorm[threadIdx.x];
    __syncthreads();

    const float rn = g_rnorm[row];
    float bv = 3.4e38f; int bi = 0;
#pragma unroll
    for (int j = 0; j < 8; j++) {
        int i = j * 32 + lane;                   // ascending per lane
        float dot2 = g_dots[(size_t)row * Sn + i];         // = 2 * f.c_i
        float v = __fadd_rn(__fsub_rn(rn, dot2), cn_s[i]); // (A-B)+C, no FMA
        if (v < bv) { bv = v; bi = i; }          // first min per lane
    }
#pragma unroll
    for (int off = 16; off; off >>= 1) {
        float ov = __shfl_xor_sync(0xffffffffu, bv, off);
        int   oi = __shfl_xor_sync(0xffffffffu, bi, off);
        if (ov < bv || (ov == bv && oi < bi)) { bv = ov; bi = oi; }
    }
    if (lane == 0) {
        g_idx[row] = bi;
        dout[IOFF + row] = (float)bi;
        part[wid] = bv;                          // ||f - c*||^2 (quantized)
    }
    const float4* c4 = (const float4*)(codebook + (size_t)bi * Dn);
    float4* o4 = (float4*)(dout + (size_t)row * Dn);
#pragma unroll
    for (int j = 0; j < 8; j++) o4[j*32 + lane] = __ldg(c4 + j*32 + lane);

    __syncthreads();
    if (threadIdx.x == 0) {
        float s = 0.f;
#pragma unroll
        for (int w = 0; w < 8; w++) s += part[w];
        g_mse_arr[blockIdx.x] = s;
    }
}

// ---------------- launch #4 (profiled): persistent GRU ------------------------
// CTA owns 7 consecutive d's. Warp w covers k in [64w, 64w+64) for ALL 7 d's
// (lane = batch). h lives in gmem [k][b] and is read ONCE per CTA per step via
// coalesced .cg loads — no smem staging, no cross-warp h re-reads. W rows stay
// L1-resident (84 KB, smem only 43 KB). 16 k-partials combined in smem; 7
// combine warps do gates. One syncthreads pair + one global barrier per step.
__device__ __forceinline__ unsigned ld_acquire_u32(const unsigned* p) {
    unsigned v;
    asm volatile("ld.acquire.gpu.u32 %0, [%1];" : "=r"(v) : "l"(p) : "memory");
    return v;
}

__global__ __launch_bounds__(GRU_THREADS, 1)
void gru_kernel(const float* __restrict__ W_hh, const float* __restrict__ b_hh)
{
    __shared__ float part_s[NW*DPC*3*32];     // 43008 B
    const int tid  = threadIdx.x;
    const int w    = tid >> 5, lane = tid & 31;
    const int dbase = blockIdx.x * DPC;
    const int k0   = w * KSEG;

    // W row-offset table (clamped for the tail CTA's OOB d's)
    int woff[DPC];
#pragma unroll
    for (int p = 0; p < DPC; p++) {
        int dd = dbase + p; if (dd > Dn-1) dd = Dn-1;
        woff[p] = (dd - dbase) * (Dn/4);
    }
    const float4* wr = (const float4*)(W_hh + ((size_t)0*Dn + dbase)*Dn + k0);
    const float4* wz = (const float4*)(W_hh + ((size_t)1*Dn + dbase)*Dn + k0);
    const float4* wn = (const float4*)(W_hh + ((size_t)2*Dn + dbase)*Dn + k0);

    // combine-thread role: warp w < 7 handles d = dbase + w, b = lane
    const int  dcomb = dbase + w;
    const bool comb  = (w < DPC) && (dcomb < Dn);
    float bh_r = 0.f, bh_z = 0.f, bh_n = 0.f;
    if (comb) {
        bh_r = b_hh[dcomb]; bh_z = b_hh[Dn + dcomb]; bh_n = b_hh[2*Dn + dcomb];
    }

    for (int t = 0; t < Tn; t++) {
        const float* hcur = g_hT2[t & 1];
        float*       hnxt = g_hT2[(t + 1) & 1];

        // prefetch GI + hprev for the combine role (hidden under the dot loop)
        float gir = 0.f, giz = 0.f, gin = 0.f, hprev = 0.f;
        if (comb) {
            int code = __ldg(g_idx + lane * Tn + t);
            const float* gi = g_GI + (size_t)code * (3*Dn);
            gir   = __ldcg(gi + dcomb);
            giz   = __ldcg(gi + Dn + dcomb);
            gin   = __ldcg(gi + 2*Dn + dcomb);
            hprev = __ldcg(hcur + dcomb * Bn + lane);
        }

        // dot products: 7 d x 3 gates over this warp's 64 k's
        float ar[DPC], az[DPC], an[DPC];
#pragma unroll
        for (int p = 0; p < DPC; p++) { ar[p] = 0.f; az[p] = 0.f; an[p] = 0.f; }
        const float* hb = hcur + k0 * Bn + lane;
#pragma unroll 2
        for (int q = 0; q < KSEG/4; q++) {
            float h0 = __ldcg(hb + (q*4+0)*Bn);
            float h1 = __ldcg(hb + (q*4+1)*Bn);
            float h2 = __ldcg(hb + (q*4+2)*Bn);
            float h3 = __ldcg(hb + (q*4+3)*Bn);
#pragma unroll
            for (int p = 0; p < DPC; p++) {
                float4 w1 = __ldg(wr + woff[p] + q);
                float4 w2 = __ldg(wz + woff[p] + q);
                float4 w3 = __ldg(wn + woff[p] + q);
                ar[p] += w1.x*h0 + w1.y*h1 + w1.z*h2 + w1.w*h3;
                az[p] += w2.x*h0 + w2.y*h1 + w2.z*h2 + w2.w*h3;
                an[p] += w3.x*h0 + w3.y*h1 + w3.z*h2 + w3.w*h3;
            }
        }
        // publish partials: part[w][p][g][lane]
#pragma unroll
        for (int p = 0; p < DPC; p++) {
            int base = ((w*DPC + p)*3)*32 + lane;
            part_s[base     ] = ar[p];
            part_s[base + 32] = az[p];
            part_s[base + 64] = an[p];
        }
        __syncthreads();

        if (comb) {
            float sr = 0.f, sz = 0.f, sn = 0.f;
#pragma unroll
            for (int ww = 0; ww < NW; ww++) {
                int base = ((ww*DPC + w)*3)*32 + lane;
                sr += part_s[base     ];
                sz += part_s[base + 32];
                sn += part_s[base + 64];
            }
            float r = 1.f / (1.f + expf(-(sr + bh_r + gir)));
            float z = 1.f / (1.f + expf(-(sz + bh_z + giz)));
            float n = tanhf(gin + r * (sn + bh_n));
            float hnew = (1.f - z) * n + z * hprev;
            hnxt[dcomb * Bn + lane] = hnew;
            g_H[((size_t)t * Bn + lane) * Dn + dcomb] = hnew;
        }
        __syncthreads();                         // h writes + part_s reuse safe
        if (tid == 0) {
            __threadfence();                     // release (covers CTA stores)
            atomicAdd(&g_bar, 1u);
            unsigned target = (unsigned)GRU_CTAS * (unsigned)(t + 1);
            while (ld_acquire_u32(&g_bar) < target) { }
        }
        __syncthreads();
    }
}

// ---------------- CP loss per (k,t) ------------------------------------------
__global__ void cploss_kernel(const float* __restrict__ features,
                              const int* __restrict__ neg_idx)
{
    int t  = blockIdx.x;            // 0..Tn-2
    int kf = blockIdx.y;            // 0..KF-1
    int k  = kf + 1;
    int slot = kf * (Tn - 1) + t;
    if (t >= Tn - k) { if (threadIdx.x == 0) g_cp_arr[slot] = 0.f; return; }

    __shared__ float sig_s[Bn];
    int wid = threadIdx.x >> 5, lane = threadIdx.x & 31;
#pragma unroll
    for (int bi = 0; bi < 4; bi++) {
        int b = wid * 4 + bi;
        const float4* hp = (const float4*)(g_Hp + ((size_t)t * Bn + b) * Dn);
        const float4* fp = (const float4*)(features + ((size_t)b * Tn + (t + k)) * Dn);
        int bneg = neg_idx[((size_t)kf * Tn + t) * Bn + b];
        const float4* fn = (const float4*)(features + ((size_t)bneg * Tn + t) * Dn);
        float s = 0.f;
#pragma unroll
        for (int j = 0; j < 8; j++) {
            float4 h4 = hp[j*32 + lane];
            float4 p4 = fp[j*32 + lane];
            float4 n4 = fn[j*32 + lane];
            s += h4.x*(p4.x-n4.x) + h4.y*(p4.y-n4.y)
               + h4.z*(p4.z-n4.z) + h4.w*(p4.w-n4.w);
        }
#pragma unroll
        for (int off = 16; off; off >>= 1) s += __shfl_xor_sync(0xffffffffu, s, off);
        if (lane == 0) sig_s[b] = 1.f / (1.f + expf(-s));
    }
    __syncthreads();
    if (threadIdx.x == 0) {
        float m = 0.f;
#pragma unroll
        for (int b = 0; b < Bn; b++) m += sig_s[b];
        g_cp_arr[slot] = -logf(m * (1.f / (float)Bn));
    }
}

// ---------------- final deterministic reduction -------------------------------
__global__ void finalize_kernel(float* __restrict__ dout) {
    __shared__ float red[256];
    int tid = threadIdx.x;
    float s = 0.f;
    for (int i = tid; i < KF*(Tn-1); i += 256) s += g_cp_arr[i];
    red[tid] = s; __syncthreads();
    for (int o = 128; o; o >>= 1) { if (tid < o) red[tid] += red[tid+o]; __syncthreads(); }
    float cp = red[0]; __syncthreads();
    float m = 0.f;
    for (int i = tid; i < Mrows/8; i += 256) m += g_mse_arr[i];
    red[tid] = m; __syncthreads();
    for (int o = 128; o; o >>= 1) { if (tid < o) red[tid] += red[tid+o]; __syncthreads(); }
    if (tid == 0) {
        float mse = red[0] / ((float)Mrows * (float)Dn);
        dout[LOFF] = cp / (float)(KF * (Tn - KF)) + 1.25f * mse;
    }
}

// ---------------- launch --------------------------------------------------------
extern "C" void kernel_launch(void* const* d_in, const int* in_sizes, int n_in,
                              void* d_out, int out_size) {
    (void)in_sizes; (void)n_in; (void)out_size;
    const float* features = (const float*)d_in[0];
    const float* codebook = (const float*)d_in[1];
    const float* W_ih     = (const float*)d_in[2];
    const float* W_hh     = (const float*)d_in[3];
    const float* b_ih     = (const float*)d_in[4];
    const float* b_hh     = (const float*)d_in[5];
    const float* W_p      = (const float*)d_in[6];
    const float* b_p      = (const float*)d_in[7];
    const int*   neg_idx  = (const int*)d_in[8];
    float* dout = (float*)d_out;

    void *p_dots, *p_GI, *p_H, *p_Hp, *p_zb;
    cudaGetSymbolAddress(&p_dots,  g_dots);
    cudaGetSymbolAddress(&p_GI,    g_GI);
    cudaGetSymbolAddress(&p_H,     g_H);
    cudaGetSymbolAddress(&p_Hp,    g_Hp);
    cudaGetSymbolAddress(&p_zb,    g_zbias);

    // #1: rownorms + h0/bar init
    prep_kernel<<<4096 + 32 + 128, 256>>>(features, codebook);

    // #2: fused GEMM — dots = 2*F C^T (bit-identical chain) and
    //                  GI = codebook @ W_ih^T + b_ih
    sgemm_fused<<<DOTS_BLKS + 48, 256>>>(
        features, codebook, (float*)p_dots, (const float*)p_zb, Dn, 2.0f, Sn,
        codebook, W_ih,     (float*)p_GI,   b_ih,               Dn, 1.0f, 3*Dn);

    // #3: argmin + quantized gather + mse partials
    argmin_kernel<<<Mrows/8, 256>>>(codebook, dout);

    // #4 (profiled): persistent GRU recurrence
    gru_kernel<<<GRU_CTAS, GRU_THREADS>>>(W_hh, b_hh);

    // #5: Hp = H @ W_p^T + b_p
    sgemm_nt<<<dim3(Dn/128, Mrows/128), 256>>>(
        (const float*)p_H, W_p, (float*)p_Hp, b_p, Mrows, Dn, Dn, 1.0f);

    // #6: CP loss terms
    cploss_kernel<<<dim3(Tn-1, KF), 256>>>(features, neg_idx);

    // #7: deterministic final reduction
    finalize_kernel<<<1, 256>>>(dout);
}

// round 13
// speedup vs baseline: 1.8986x; 1.0849x over previous
#include <cuda_runtime.h>
#include <math.h>
#include <stdint.h>
#include <stddef.h>

// ---------------- problem constants ----------------
#define Bn   32
#define Tn   1024
#define Dn   1024
#define Sn   256
#define KF   3
#define Mrows (Bn*Tn)                 // 32768
#define IOFF  ((size_t)Bn*Tn*Dn)      // indices start in d_out
#define LOFF  (IOFF + (size_t)Bn*Tn)  // total scalar slot

// ---------------- GRU step-GEMM config ----------------
#define GCTAS   144                   // 24 m-tiles x 6 k-splits (all co-resident)
#define WS_STRIDE 132                 // padded W smem row (floats)
#define HS_STRIDE 36                  // padded h smem row (floats)
#define WS_OFF  0
#define HS_OFF  (176*WS_STRIDE)                  // 23232
#define MG_OFF  (HS_OFF + 176*HS_STRIDE)         // 29568
#define GRU_SMEM ((MG_OFF + 128*36)*4)           // 136704 B

// ---------------- device scratch (no allocations) ----------------
__device__ float g_dots[(size_t)Mrows * Sn];     // 2*F.C^T
__device__ float g_Hbuf[(size_t)(Tn+1)*Bn*Dn];   // h history, slot 0 = zeros
__device__ float g_Hp  [(size_t)Mrows * Dn];
__device__ float g_GI  [(size_t)Sn * 3*Dn];      // codebook @ W_ih^T + b_ih
__device__ float g_hkb [Dn*Bn];                  // current h transposed [k][b]
__device__ float g_part[6][Bn][3*Dn];            // k-split gh partials
__device__ float g_rnorm[Mrows];
__device__ float g_cnorm[Sn];
__device__ float g_zbias[Sn];
__device__ int   g_idx[Mrows];                   // row = b*Tn + t
__device__ float g_mse_arr[Mrows/8];
__device__ float g_cp_arr[KF*(Tn-1)];
__device__ unsigned g_bar;

// ---------------- launch #1: rownorms + h/bar init -----------------------------
__global__ void prep_kernel(const float* __restrict__ features,
                            const float* __restrict__ codebook) {
    int bx = blockIdx.x;
    if (bx < 4096 + 32) {
        const float* X = (bx < 4096) ? features : codebook;
        float* out     = (bx < 4096) ? g_rnorm : g_cnorm;
        int base       = (bx < 4096) ? bx * 8 : (bx - 4096) * 8;
        int wid = threadIdx.x >> 5, lane = threadIdx.x & 31;
        int row = base + wid;
        const float4* x = (const float4*)(X + (size_t)row * Dn);
        float s = 0.f;
#pragma unroll
        for (int j = 0; j < 8; j++) {
            float4 v = x[j*32 + lane];
            s += v.x*v.x + v.y*v.y + v.z*v.z + v.w*v.w;
        }
#pragma unroll
        for (int off = 16; off; off >>= 1) s += __shfl_xor_sync(0xffffffffu, s, off);
        if (lane == 0) out[row] = s;
    } else {
        int i = (bx - 4128) * 256 + threadIdx.x;
        if (i < Bn*Dn)            g_Hbuf[i] = 0.f;         // slot 0 = h(0) = 0
        else if (i < 2*Bn*Dn)     g_hkb[i - Bn*Dn] = 0.f;
        if (bx == gridDim.x - 1 && threadIdx.x == 0) g_bar = 0u;
    }
}

// ---------------- launch #2: fused SGEMM (dots + GI) ---------------------------
// C = alpha*A*B^T + bias[col]; FFMA chain identical to the proven kernel ->
// dots (hence argmin/indices) bit-identical.
#define DOTS_BLKS 512
__global__ __launch_bounds__(256, 2)
void sgemm_fused(const float* __restrict__ A1, const float* __restrict__ B1,
                 float* __restrict__ C1, const float* __restrict__ bias1,
                 int K1, float alpha1, int N1,
                 const float* __restrict__ A2, const float* __restrict__ B2,
                 float* __restrict__ C2, const float* __restrict__ bias2,
                 int K2, float alpha2, int N2)
{
    __shared__ float As[16][128];
    __shared__ float Bs[16][128];
    const int tid = threadIdx.x;
    const int tx = tid & 15, ty = tid >> 4;

    const float *A, *Bm, *bias; float *C;
    int K, N, bxn, byn; float alpha;
    if (blockIdx.x < DOTS_BLKS) {
        A = A1; Bm = B1; C = C1; bias = bias1; K = K1; N = N1; alpha = alpha1;
        bxn = blockIdx.x & 1;  byn = blockIdx.x >> 1;
    } else {
        int i = blockIdx.x - DOTS_BLKS;
        A = A2; Bm = B2; C = C2; bias = bias2; K = K2; N = N2; alpha = alpha2;
        bxn = i % 24;          byn = i / 24;
    }
    const float* Ab = A  + (size_t)byn * 128 * K;
    const float* Bb = Bm + (size_t)bxn * 128 * K;

    float acc[8][8];
#pragma unroll
    for (int i = 0; i < 8; i++)
#pragma unroll
        for (int j = 0; j < 8; j++) acc[i][j] = 0.f;

    for (int kt = 0; kt < K; kt += 16) {
#pragma unroll
        for (int r = 0; r < 2; r++) {
            int f   = tid + r * 256;
            int row = f >> 2;
            int c4  = (f & 3) << 2;
            float4 va = *(const float4*)(Ab + (size_t)row * K + kt + c4);
            As[c4+0][row] = va.x; As[c4+1][row] = va.y;
            As[c4+2][row] = va.z; As[c4+3][row] = va.w;
            float4 vb = *(const float4*)(Bb + (size_t)row * K + kt + c4);
            Bs[c4+0][row] = vb.x; Bs[c4+1][row] = vb.y;
            Bs[c4+2][row] = vb.z; Bs[c4+3][row] = vb.w;
        }
        __syncthreads();
#pragma unroll
        for (int kk = 0; kk < 16; kk++) {
            float a[8], b[8];
            *(float4*)&a[0] = *(const float4*)&As[kk][ty*8];
            *(float4*)&a[4] = *(const float4*)&As[kk][ty*8+4];
            *(float4*)&b[0] = *(const float4*)&Bs[kk][tx*8];
            *(float4*)&b[4] = *(const float4*)&Bs[kk][tx*8+4];
#pragma unroll
            for (int i = 0; i < 8; i++)
#pragma unroll
                for (int j = 0; j < 8; j++) acc[i][j] += a[i] * b[j];
        }
        __syncthreads();
    }
#pragma unroll
    for (int i = 0; i < 8; i++) {
        size_t row = (size_t)byn * 128 + ty*8 + i;
#pragma unroll
        for (int j = 0; j < 8; j += 4) {
            int col = bxn * 128 + tx*8 + j;
            float4 o;
            o.x = alpha * acc[i][j+0] + bias[col+0];
            o.y = alpha * acc[i][j+1] + bias[col+1];
            o.z = alpha * acc[i][j+2] + bias[col+2];
            o.w = alpha * acc[i][j+3] + bias[col+3];
            *(float4*)(C + row * (size_t)N + col) = o;
        }
    }
}

// ---------------- plain SGEMM (Hp) — proven fp32-roofline version ---------------
__global__ __launch_bounds__(256, 2)
void sgemm_nt(const float* __restrict__ A, const float* __restrict__ Bm,
              float* __restrict__ C, const float* __restrict__ bias,
              int M, int N, int K, float alpha)
{
    __shared__ float As[16][128];
    __shared__ float Bs[16][128];
    const int tid = threadIdx.x;
    const int tx = tid & 15, ty = tid >> 4;
    const float* Ab = A + (size_t)blockIdx.y * 128 * K;
    const float* Bb = Bm + (size_t)blockIdx.x * 128 * K;

    float acc[8][8];
#pragma unroll
    for (int i = 0; i < 8; i++)
#pragma unroll
        for (int j = 0; j < 8; j++) acc[i][j] = 0.f;

    for (int kt = 0; kt < K; kt += 16) {
#pragma unroll
        for (int r = 0; r < 2; r++) {
            int f   = tid + r * 256;
            int row = f >> 2;
            int c4  = (f & 3) << 2;
            float4 va = *(const float4*)(Ab + (size_t)row * K + kt + c4);
            As[c4+0][row] = va.x; As[c4+1][row] = va.y;
            As[c4+2][row] = va.z; As[c4+3][row] = va.w;
            float4 vb = *(const float4*)(Bb + (size_t)row * K + kt + c4);
            Bs[c4+0][row] = vb.x; Bs[c4+1][row] = vb.y;
            Bs[c4+2][row] = vb.z; Bs[c4+3][row] = vb.w;
        }
        __syncthreads();
#pragma unroll
        for (int kk = 0; kk < 16; kk++) {
            float a[8], b[8];
            *(float4*)&a[0] = *(const float4*)&As[kk][ty*8];
            *(float4*)&a[4] = *(const float4*)&As[kk][ty*8+4];
            *(float4*)&b[0] = *(const float4*)&Bs[kk][tx*8];
            *(float4*)&b[4] = *(const float4*)&Bs[kk][tx*8+4];
#pragma unroll
            for (int i = 0; i < 8; i++)
#pragma unroll
                for (int j = 0; j < 8; j++) acc[i][j] += a[i] * b[j];
        }
        __syncthreads();
    }
#pragma unroll
    for (int i = 0; i < 8; i++) {
        size_t row = (size_t)blockIdx.y * 128 + ty*8 + i;
#pragma unroll
        for (int j = 0; j < 8; j += 4) {
            int col = blockIdx.x * 128 + tx*8 + j;
            float4 o;
            o.x = alpha * acc[i][j+0] + bias[col+0];
            o.y = alpha * acc[i][j+1] + bias[col+1];
            o.z = alpha * acc[i][j+2] + bias[col+2];
            o.w = alpha * acc[i][j+3] + bias[col+3];
            *(float4*)(C + row * (size_t)N + col) = o;
        }
    }
}

// ---------------- launch #3: argmin (reference-exact) + gather + mse -----------
__global__ void argmin_kernel(const float* __restrict__ codebook,
                              float* __restrict__ dout) {
    int wid = threadIdx.x >> 5, lane = threadIdx.x & 31;
    int row = blockIdx.x * 8 + wid;
    __shared__ float part[8];
    __shared__ float cn_s[Sn];
    if (threadIdx.x < Sn) cn_s[threadIdx.x] = g_cnorm[threadIdx.x];
    __syncthreads();

    const float rn = g_rnorm[row];
    float bv = 3.4e38f; int bi = 0;
#pragma unroll
    for (int j = 0; j < 8; j++) {
        int i = j * 32 + lane;
        float dot2 = g_dots[(size_t)row * Sn + i];
        float v = __fadd_rn(__fsub_rn(rn, dot2), cn_s[i]);
        if (v < bv) { bv = v; bi = i; }
    }
#pragma unroll
    for (int off = 16; off; off >>= 1) {
        float ov = __shfl_xor_sync(0xffffffffu, bv, off);
        int   oi = __shfl_xor_sync(0xffffffffu, bi, off);
        if (ov < bv || (ov == bv && oi < bi)) { bv = ov; bi = oi; }
    }
    if (lane == 0) {
        g_idx[row] = bi;
        dout[IOFF + row] = (float)bi;
        part[wid] = bv;
    }
    const float4* c4 = (const float4*)(codebook + (size_t)bi * Dn);
    float4* o4 = (float4*)(dout + (size_t)row * Dn);
#pragma unroll
    for (int j = 0; j < 8; j++) o4[j*32 + lane] = __ldg(c4 + j*32 + lane);

    __syncthreads();
    if (threadIdx.x == 0) {
        float s = 0.f;
#pragma unroll
        for (int w = 0; w < 8; w++) s += part[w];
        g_mse_arr[blockIdx.x] = s;
    }
}

// ---------------- launch #4 (profiled): persistent GRU step-GEMM ---------------
// 144 CTAs = 24 m-tiles(128) x 6 k-splits (176,176,176,176,160,160).
// W-tile staged in smem ONCE. Per step: stage h slice from g_hkb[k][b];
// 128x32xK smem GEMM (8m x 4b thread tiles, 2 k-teams); partials -> g_part;
// barrier; gates on the 32 short-split CTAs (lane = d, all coalesced);
// h -> g_Hbuf[t+1] + transposed g_hkb; barrier.
__device__ __forceinline__ unsigned ld_acquire_u32(const unsigned* p) {
    unsigned v;
    asm volatile("ld.acquire.gpu.u32 %0, [%1];" : "=r"(v) : "l"(p) : "memory");
    return v;
}

__global__ __launch_bounds__(256, 1)
void gru_step(const float* __restrict__ Wf, const float* __restrict__ bhh)
{
    extern __shared__ float sm[];
    float* Ws = sm + WS_OFF;            // [ksz][132]
    float* hs = sm + HS_OFF;            // [ksz][36]
    float* mg = sm + MG_OFF;            // [128][36] merge buf / gate transpose

    const int tid  = threadIdx.x;
    const int team = tid >> 7, ttid = tid & 127;
    const int tm = ttid >> 3, tb = ttid & 7;
    const int bid = blockIdx.x;
    const int mt = bid / 6, ks = bid - mt * 6;
    const int ksz  = (ks < 4) ? 176 : 160;
    const int k0   = (ks < 4) ? ks * 176 : 704 + (ks - 4) * 160;
    const int m0   = mt * 128;
    const int kmid = (ks < 4) ? 96 : 80;
    const int kbeg = team ? kmid : 0;
    const int kend = team ? ksz : kmid;

    // gate role lives on short-split CTAs (GEMM slack absorbs gate work)
    int gidx = -1;
    if (ks == 4) gidx = mt;
    else if (ks == 5 && mt < 8) gidx = 24 + mt;
    const int d0   = gidx * 32;
    const int wv   = tid >> 5, lane = tid & 31;
    float bhr = 0.f, bhz = 0.f, bhn = 0.f;
    if (gidx >= 0) {
        bhr = __ldg(bhh + d0 + lane);
        bhz = __ldg(bhh + Dn + d0 + lane);
        bhn = __ldg(bhh + 2*Dn + d0 + lane);
    }

    // ---- stage W tile once (transposed into [k][m], padded rows) ----
    for (int m = 0; m < 128; m++)
        for (int kk = tid; kk < ksz; kk += 256)
            Ws[kk*WS_STRIDE + m] = __ldg(Wf + (size_t)(m0 + m) * Dn + k0 + kk);
    __syncthreads();

    for (int t = 0; t < Tn; t++) {
        // ---- stage h slice: g_hkb[k][b] (.cg, cross-SM data) ----
        for (int i = tid; i < ksz * 8; i += 256) {
            int kk = i >> 3, bq = i & 7;
            float4 v = __ldcg((const float4*)(g_hkb + (k0 + kk) * 32 + bq * 4));
            float* dst = hs + kk * HS_STRIDE + bq * 4;
            dst[0] = v.x; dst[1] = v.y; dst[2] = v.z; dst[3] = v.w;
        }
        __syncthreads();

        // ---- 128x32 GEMM over this team's k range ----
        float acc[8][4];
#pragma unroll
        for (int i = 0; i < 8; i++)
#pragma unroll
            for (int j = 0; j < 4; j++) acc[i][j] = 0.f;

#pragma unroll 2
        for (int kk = kbeg; kk < kend; kk++) {
            float4 w0 = *(const float4*)(Ws + kk*WS_STRIDE + tm*8);
            float4 w1 = *(const float4*)(Ws + kk*WS_STRIDE + tm*8 + 4);
            float4 hv = *(const float4*)(hs + kk*HS_STRIDE + tb*4);
            float wa[8] = {w0.x, w0.y, w0.z, w0.w, w1.x, w1.y, w1.z, w1.w};
            float hb[4] = {hv.x, hv.y, hv.z, hv.w};
#pragma unroll
            for (int i = 0; i < 8; i++)
#pragma unroll
                for (int j = 0; j < 4; j++) acc[i][j] += wa[i] * hb[j];
        }

        // ---- merge teams + store partials ----
        if (team == 1) {
#pragma unroll
            for (int i = 0; i < 8; i++) {
                float4 o; o.x = acc[i][0]; o.y = acc[i][1]; o.z = acc[i][2]; o.w = acc[i][3];
                *(float4*)(mg + (tm*8 + i) * 36 + tb*4) = o;
            }
        }
        __syncthreads();
        if (team == 0) {
#pragma unroll
            for (int i = 0; i < 8; i++) {
                float4 o = *(const float4*)(mg + (tm*8 + i) * 36 + tb*4);
                acc[i][0] += o.x; acc[i][1] += o.y; acc[i][2] += o.z; acc[i][3] += o.w;
            }
#pragma unroll
            for (int j = 0; j < 4; j++) {
                int b = tb * 4 + j;
                float4 s0, s1;
                s0.x = acc[0][j]; s0.y = acc[1][j]; s0.z = acc[2][j]; s0.w = acc[3][j];
                s1.x = acc[4][j]; s1.y = acc[5][j]; s1.z = acc[6][j]; s1.w = acc[7][j];
                float* dst = &g_part[ks][b][m0 + tm*8];
                *(float4*)dst       = s0;
                *(float4*)(dst + 4) = s1;
            }
        }
        __syncthreads();
        if (tid == 0) {
            __threadfence();
            atomicAdd(&g_bar, 1u);
            unsigned tgt = (unsigned)GCTAS * (unsigned)(2*t + 1);
            while (ld_acquire_u32(&g_bar) < tgt) {}
        }
        __syncthreads();

        // ---- gate phase (32 designated CTAs; 32 d x 32 b each) ----
        if (gidx >= 0) {
            float* ht = mg;                      // [32][33] transpose tile
#pragma unroll
            for (int jj = 0; jj < 4; jj++) {
                int b = wv * 4 + jj;
                int code = __ldg(g_idx + b * Tn + t);
                float sr = bhr, sz = bhz, sn = bhn;
#pragma unroll
                for (int s = 0; s < 6; s++) {
                    const float* q = &g_part[s][b][0];
                    sr += __ldcg(q +          d0 + lane);
                    sz += __ldcg(q + Dn     + d0 + lane);
                    sn += __ldcg(q + 2*Dn   + d0 + lane);
                }
                const float* gi = g_GI + (size_t)code * (3*Dn);
                float r = 1.f / (1.f + expf(-(sr + __ldcg(gi + d0 + lane))));
                float z = 1.f / (1.f + expf(-(sz + __ldcg(gi + Dn + d0 + lane))));
                float n = tanhf(__ldcg(gi + 2*Dn + d0 + lane) + r * sn);
                float hp = g_Hbuf[(size_t)t * (Bn*Dn) + b * Dn + d0 + lane];
                float hn = (1.f - z) * n + z * hp;
                g_Hbuf[(size_t)(t + 1) * (Bn*Dn) + b * Dn + d0 + lane] = hn;
                ht[lane * 33 + b] = hn;
            }
            __syncthreads();                     // uniform: whole CTA is gate CTA
#pragma unroll
            for (int jj = 0; jj < 4; jj++) {
                int dd = wv * 4 + jj;
                g_hkb[(d0 + dd) * 32 + lane] = ht[dd * 33 + lane];
            }
        }
        __syncthreads();
        if (tid == 0) {
            __threadfence();
            atomicAdd(&g_bar, 1u);
            unsigned tgt = (unsigned)GCTAS * (unsigned)(2*t + 2);
            while (ld_acquire_u32(&g_bar) < tgt) {}
        }
        __syncthreads();
    }
}

// ---------------- CP loss per (k,t) ---------------------------------------------
__global__ void cploss_kernel(const float* __restrict__ features,
                              const int* __restrict__ neg_idx)
{
    int t  = blockIdx.x;
    int kf = blockIdx.y;
    int k  = kf + 1;
    int slot = kf * (Tn - 1) + t;
    if (t >= Tn - k) { if (threadIdx.x == 0) g_cp_arr[slot] = 0.f; return; }

    __shared__ float sig_s[Bn];
    int wid = threadIdx.x >> 5, lane = threadIdx.x & 31;
#pragma unroll
    for (int bi = 0; bi < 4; bi++) {
        int b = wid * 4 + bi;
        const float4* hp = (const float4*)(g_Hp + ((size_t)t * Bn + b) * Dn);
        const float4* fp = (const float4*)(features + ((size_t)b * Tn + (t + k)) * Dn);
        int bneg = neg_idx[((size_t)kf * Tn + t) * Bn + b];
        const float4* fn = (const float4*)(features + ((size_t)bneg * Tn + t) * Dn);
        float s = 0.f;
#pragma unroll
        for (int j = 0; j < 8; j++) {
            float4 h4 = hp[j*32 + lane];
            float4 p4 = fp[j*32 + lane];
            float4 n4 = fn[j*32 + lane];
            s += h4.x*(p4.x-n4.x) + h4.y*(p4.y-n4.y)
               + h4.z*(p4.z-n4.z) + h4.w*(p4.w-n4.w);
        }
#pragma unroll
        for (int off = 16; off; off >>= 1) s += __shfl_xor_sync(0xffffffffu, s, off);
        if (lane == 0) sig_s[b] = 1.f / (1.f + expf(-s));
    }
    __syncthreads();
    if (threadIdx.x == 0) {
        float m = 0.f;
#pragma unroll
        for (int b = 0; b < Bn; b++) m += sig_s[b];
        g_cp_arr[slot] = -logf(m * (1.f / (float)Bn));
    }
}

// ---------------- final deterministic reduction ----------------------------------
__global__ void finalize_kernel(float* __restrict__ dout) {
    __shared__ float red[256];
    int tid = threadIdx.x;
    float s = 0.f;
    for (int i = tid; i < KF*(Tn-1); i += 256) s += g_cp_arr[i];
    red[tid] = s; __syncthreads();
    for (int o = 128; o; o >>= 1) { if (tid < o) red[tid] += red[tid+o]; __syncthreads(); }
    float cp = red[0]; __syncthreads();
    float m = 0.f;
    for (int i = tid; i < Mrows/8; i += 256) m += g_mse_arr[i];
    red[tid] = m; __syncthreads();
    for (int o = 128; o; o >>= 1) { if (tid < o) red[tid] += red[tid+o]; __syncthreads(); }
    if (tid == 0) {
        float mse = red[0] / ((float)Mrows * (float)Dn);
        dout[LOFF] = cp / (float)(KF * (Tn - KF)) + 1.25f * mse;
    }
}

// ---------------- launch ----------------------------------------------------------
extern "C" void kernel_launch(void* const* d_in, const int* in_sizes, int n_in,
                              void* d_out, int out_size) {
    (void)in_sizes; (void)n_in; (void)out_size;
    const float* features = (const float*)d_in[0];
    const float* codebook = (const float*)d_in[1];
    const float* W_ih     = (const float*)d_in[2];
    const float* W_hh     = (const float*)d_in[3];
    const float* b_ih     = (const float*)d_in[4];
    const float* b_hh     = (const float*)d_in[5];
    const float* W_p      = (const float*)d_in[6];
    const float* b_p      = (const float*)d_in[7];
    const int*   neg_idx  = (const int*)d_in[8];
    float* dout = (float*)d_out;

    void *p_dots, *p_GI, *p_Hbuf, *p_Hp, *p_zb;
    cudaGetSymbolAddress(&p_dots, g_dots);
    cudaGetSymbolAddress(&p_GI,   g_GI);
    cudaGetSymbolAddress(&p_Hbuf, g_Hbuf);
    cudaGetSymbolAddress(&p_Hp,   g_Hp);
    cudaGetSymbolAddress(&p_zb,   g_zbias);
    const float* p_H = (const float*)p_Hbuf + (size_t)Bn * Dn;  // slots 1..Tn

    cudaFuncSetAttribute(gru_step,
        cudaFuncAttributeMaxDynamicSharedMemorySize, GRU_SMEM);

    // #1: rownorms + h/bar init
    prep_kernel<<<4096 + 32 + 256, 256>>>(features, codebook);

    // #2: fused GEMM — dots = 2*F C^T (bit-identical chain) and GI
    sgemm_fused<<<DOTS_BLKS + 48, 256>>>(
        features, codebook, (float*)p_dots, (const float*)p_zb, Dn, 2.0f, Sn,
        codebook, W_ih,     (float*)p_GI,   b_ih,               Dn, 1.0f, 3*Dn);

    // #3: argmin + quantized gather + mse partials
    argmin_kernel<<<Mrows/8, 256>>>(codebook, dout);

    // #4 (profiled): persistent GRU step-GEMM
    gru_step<<<GCTAS, 256, GRU_SMEM>>>(W_hh, b_hh);

    // #5: Hp = H @ W_p^T + b_p
    sgemm_nt<<<dim3(Dn/128, Mrows/128), 256>>>(
        p_H, W_p, (float*)p_Hp, b_p, Mrows, Dn, Dn, 1.0f);

    // #6: CP loss terms
    cploss_kernel<<<dim3(Tn-1, KF), 256>>>(features, neg_idx);

    // #7: deterministic final reduction
    finalize_kernel<<<1, 256>>>(dout);
}